// round 11
// baseline (speedup 1.0000x reference)
#include <cuda_runtime.h>
#include <cstdint>

#define NB 4
#define SQ 1024
#define DM 1280
#define NH 16
#define HD 80
#define MTOT (NB*SQ)      // 4096
#define NQKV (3*DM)       // 3840
#define NROWS (NB*NH*SQ)  // 65536
#define QPAD 96           // int8 q/k rows padded 80 -> 96

// ---------------------------------------------------------------------------
// Scratch (__device__ globals; allocation-free rule)
// ---------------------------------------------------------------------------
__device__ float g_q[NROWS*HD];
__device__ float g_k[NROWS*HD];
__device__ float g_v[NROWS*HD];
__device__ float g_ctx[MTOT*DM];

// int8 2-digit operands (xq*/sax reused for ctx; wq*/sbw reused for Wproj)
__device__ int8_t xq1_g[MTOT*DM],  xq2_g[MTOT*DM];
__device__ int8_t wq1_g[NQKV*DM],  wq2_g[NQKV*DM];
__device__ float  sax_g[MTOT];
__device__ float  sbw_g[NQKV];

// int8 2-digit rotated q/k + per-row scales
__device__ int8_t qq1_g[NROWS*QPAD], qq2_g[NROWS*QPAD];
__device__ int8_t kq1_g[NROWS*QPAD], kq2_g[NROWS*QPAD];
__device__ float  sq_g[NROWS], sk_g[NROWS];

// int8 2-digit V, transposed per head: vt[bh][d][s], + per-(bh,d) scales
__device__ int8_t vt1_g[NB*NH*HD*SQ], vt2_g[NB*NH*HD*SQ];
__device__ float  sv_g[NB*NH*HD];

// ---------------------------------------------------------------------------
// helpers
// ---------------------------------------------------------------------------
__device__ __forceinline__ uint32_t s2u(const void* p) {
    uint32_t a;
    asm("{ .reg .u64 t; cvta.to.shared.u64 t, %1; cvt.u32.u64 %0, t; }"
        : "=r"(a) : "l"(p));
    return a;
}
__device__ __forceinline__ void ldm_x4(uint32_t* r, uint32_t addr) {
    asm volatile("ldmatrix.sync.aligned.m8n8.x4.shared.b16 {%0,%1,%2,%3}, [%4];"
        : "=r"(r[0]), "=r"(r[1]), "=r"(r[2]), "=r"(r[3]) : "r"(addr));
}
__device__ __forceinline__ void mma_s8(int* c, const uint32_t* a,
                                       uint32_t b0, uint32_t b1) {
    asm volatile(
        "mma.sync.aligned.m16n8k32.row.col.s32.s8.s8.s32 "
        "{%0,%1,%2,%3}, {%4,%5,%6,%7}, {%8,%9}, {%0,%1,%2,%3};"
        : "+r"(c[0]), "+r"(c[1]), "+r"(c[2]), "+r"(c[3])
        : "r"(a[0]), "r"(a[1]), "r"(a[2]), "r"(a[3]), "r"(b0), "r"(b1));
}
__device__ __forceinline__ void cpasync16(uint32_t dst, const void* src) {
    asm volatile("cp.async.ca.shared.global [%0], [%1], 16;"
        :: "r"(dst), "l"(src) : "memory");
}
__device__ __forceinline__ void st16(uint32_t addr, int lo, int hi) {
    uint16_t v = (uint16_t)((lo & 0xFF) | ((hi & 0xFF) << 8));
    asm volatile("st.shared.u16 [%0], %1;" :: "r"(addr), "h"(v) : "memory");
}
#define CP_COMMIT() asm volatile("cp.async.commit_group;" ::: "memory")
#define CP_WAIT0()  asm volatile("cp.async.wait_group 0;" ::: "memory")
#define CP_WAIT1()  asm volatile("cp.async.wait_group 1;" ::: "memory")

// ---------------------------------------------------------------------------
// fp32 -> int8 2-digit row quantization: v = s*(d1 + d2/250), s = rowmax/120.
// ---------------------------------------------------------------------------
__global__ void __launch_bounds__(128) quant_kernel(
    const float* __restrict__ src, int8_t* __restrict__ d1,
    int8_t* __restrict__ d2, float* __restrict__ scale)
{
    const int row = blockIdx.x;
    const int tid = threadIdx.x;
    const float* p = src + (size_t)row * DM;
    float mx = 0.f;
    for (int i = tid; i < DM; i += 128) mx = fmaxf(mx, fabsf(p[i]));
    #pragma unroll
    for (int off = 16; off >= 1; off >>= 1)
        mx = fmaxf(mx, __shfl_xor_sync(0xffffffffu, mx, off));
    __shared__ float smx[4];
    if ((tid & 31) == 0) smx[tid >> 5] = mx;
    __syncthreads();
    mx = fmaxf(fmaxf(smx[0], smx[1]), fmaxf(smx[2], smx[3]));
    const float s = (mx > 0.f) ? mx * (1.f / 120.f) : 1.f;
    const float inv = 1.f / s;
    for (int i = tid; i < DM; i += 128) {
        const float f  = p[i] * inv;
        const float q1 = rintf(f);
        const float q2 = rintf(250.f * (f - q1));
        d1[(size_t)row * DM + i] = (int8_t)(int)q1;
        d2[(size_t)row * DM + i] = (int8_t)(int)q2;
    }
    if (tid == 0) scale[row] = s;
}

// ===========================================================================
// int8 2-digit GEMM core (R9/R10 validated). PROJ=false: QKV scatter epilogue
// (q,k,v fp32 head-major). PROJ=true: dense fp32 out.
// ===========================================================================
#define IK 128
#define IPITCH 144
#define IOFF_A2 (128*IPITCH)
#define IOFF_B1 (2*128*IPITCH)
#define IOFF_B2 (IOFF_B1 + 64*IPITCH)
#define ISTAGE (IOFF_B2 + 64*IPITCH)
#define IGEMM_DSMEM (2*ISTAGE)         // 110592

template<bool PROJ>
__global__ void __launch_bounds__(256, 2) gemm_i8(
    const int8_t* __restrict__ A1, const int8_t* __restrict__ A2,
    const int8_t* __restrict__ B1, const int8_t* __restrict__ B2,
    const float* __restrict__ sa_v, const float* __restrict__ sb_v,
    const float* __restrict__ bias, float* __restrict__ Cout)
{
    extern __shared__ char dsm_raw[];
    const uint32_t base = s2u(dsm_raw);

    const int tid  = threadIdx.x;
    const int wid  = tid >> 5, lane = tid & 31;
    const int bx = blockIdx.x, by = blockIdx.y;
    const int wm = wid >> 1, wn = wid & 1;    // warp tile 32(M) x 32(N)

    const int8_t* a1p = A1 + (size_t)(by * 128) * DM;
    const int8_t* a2p = A2 + (size_t)(by * 128) * DM;
    const int8_t* b1p = B1 + (size_t)(bx * 64) * DM;
    const int8_t* b2p = B2 + (size_t)(bx * 64) * DM;

    auto ISSUE = [&](int it) {
        const uint32_t sb = base + (it & 1) * ISTAGE;
        const int kof = it * IK;
        #pragma unroll
        for (int j = 0; j < 12; j++) {
            const int idx = tid + 256 * j;
            int local; uint32_t moff; const int8_t* srcp;
            if (j < 4)       { local = idx;        moff = 0;       srcp = a1p; }
            else if (j < 8)  { local = idx - 1024; moff = IOFF_A2; srcp = a2p; }
            else if (j < 10) { local = idx - 2048; moff = IOFF_B1; srcp = b1p; }
            else             { local = idx - 2560; moff = IOFF_B2; srcp = b2p; }
            const int r = local >> 3, c = local & 7;
            cpasync16(sb + moff + r * IPITCH + c * 16,
                      srcp + (size_t)r * DM + kof + c * 16);
        }
        CP_COMMIT();
    };

    int accP[2][4][4], accX[2][4][4];
    #pragma unroll
    for (int i = 0; i < 2; i++)
        #pragma unroll
        for (int j = 0; j < 4; j++)
            #pragma unroll
            for (int q = 0; q < 4; q++) { accP[i][j][q] = 0; accX[i][j][q] = 0; }

    ISSUE(0); ISSUE(1);

    const int NITI = DM / IK;
    for (int it = 0; it < NITI; ++it) {
        if (it == NITI - 1) { CP_WAIT0(); } else { CP_WAIT1(); }
        __syncthreads();

        const uint32_t sb = base + (it & 1) * ISTAGE;
        #pragma unroll
        for (int kc = 0; kc < 4; kc++) {
            uint32_t Ad1[2][4], Ad2[2][4];
            #pragma unroll
            for (int mf = 0; mf < 2; mf++) {
                const uint32_t aoff =
                    (uint32_t)((wm*32 + mf*16 + (lane & 15)) * IPITCH
                               + kc*32 + (lane >> 4) * 16);
                ldm_x4(Ad1[mf], sb + aoff);
                ldm_x4(Ad2[mf], sb + IOFF_A2 + aoff);
            }
            uint32_t Bd1[2][4], Bd2[2][4];
            #pragma unroll
            for (int g = 0; g < 2; g++) {
                const int quad = lane >> 3;
                const uint32_t boff =
                    (uint32_t)((wn*32 + g*16 + (quad >> 1) * 8 + (lane & 7)) * IPITCH
                               + kc*32 + (quad & 1) * 16);
                ldm_x4(Bd1[g], sb + IOFF_B1 + boff);
                ldm_x4(Bd2[g], sb + IOFF_B2 + boff);
            }
            #pragma unroll
            for (int mf = 0; mf < 2; mf++)
                #pragma unroll
                for (int nb = 0; nb < 4; nb++)
                    mma_s8(accP[mf][nb], Ad1[mf], Bd1[nb>>1][(nb&1)*2], Bd1[nb>>1][(nb&1)*2+1]);
            #pragma unroll
            for (int mf = 0; mf < 2; mf++)
                #pragma unroll
                for (int nb = 0; nb < 4; nb++)
                    mma_s8(accX[mf][nb], Ad1[mf], Bd2[nb>>1][(nb&1)*2], Bd2[nb>>1][(nb&1)*2+1]);
            #pragma unroll
            for (int mf = 0; mf < 2; mf++)
                #pragma unroll
                for (int nb = 0; nb < 4; nb++)
                    mma_s8(accX[mf][nb], Ad2[mf], Bd1[nb>>1][(nb&1)*2], Bd1[nb>>1][(nb&1)*2+1]);
        }
        __syncthreads();
        if (it + 2 < NITI) ISSUE(it + 2);
    }

    #pragma unroll
    for (int mf = 0; mf < 2; mf++)
        #pragma unroll
        for (int nb = 0; nb < 4; nb++)
            #pragma unroll
            for (int ci = 0; ci < 2; ci++) {
                const int m = by*128 + wm*32 + mf*16 + (lane >> 2) + ci*8;
                const int n = bx*64 + wn*32 + nb*8 + (lane & 3) * 2;
                const float sa = sa_v[m];
                float2 v;
                v.x = sa * sb_v[n]   * ((float)accP[mf][nb][2*ci+0]
                        + (float)accX[mf][nb][2*ci+0] * 0.004f) + bias[n];
                v.y = sa * sb_v[n+1] * ((float)accP[mf][nb][2*ci+1]
                        + (float)accX[mf][nb][2*ci+1] * 0.004f) + bias[n+1];
                if (PROJ) {
                    *(float2*)&Cout[(size_t)m * DM + n] = v;
                } else {
                    const int sel = n / DM;
                    const int r2  = n - sel * DM;
                    const int h   = r2 / HD;
                    const int dd  = r2 - h * HD;
                    const int bb  = m >> 10;
                    const int ss  = m & (SQ - 1);
                    const size_t di = (((size_t)bb * NH + h) * SQ + ss) * HD + dd;
                    if (sel == 0)      *(float2*)&g_q[di] = v;
                    else if (sel == 1) *(float2*)&g_k[di] = v;
                    else               *(float2*)&g_v[di] = v;
                }
            }
}

// ---------------------------------------------------------------------------
// RoPE + int8 2-digit quantization of q/k. One warp per (b,h,s) row.
// ---------------------------------------------------------------------------
__global__ void __launch_bounds__(256) rope_quant(
    const float* __restrict__ cosp, const float* __restrict__ sinp)
{
    const int row  = (blockIdx.x << 3) + (threadIdx.x >> 5);   // < NROWS
    const int lane = threadIdx.x & 31;
    const int ss   = row & (SQ - 1);
    const size_t base = (size_t)row * HD;

    const int d0 = lane;
    const bool two = lane < 8;

    const float c1 = cosp[ss*HD + d0],      s1 = sinp[ss*HD + d0];
    const float c2 = cosp[ss*HD + d0 + 40], s2 = sinp[ss*HD + d0 + 40];
    float a, b2;

    a = g_q[base + d0]; b2 = g_q[base + d0 + 40];
    float qo1 = a*c1 - b2*s1, qo2 = b2*c2 + a*s2;
    a = g_k[base + d0]; b2 = g_k[base + d0 + 40];
    float ko1 = a*c1 - b2*s1, ko2 = b2*c2 + a*s2;

    float qo3 = 0.f, qo4 = 0.f, ko3 = 0.f, ko4 = 0.f;
    if (two) {
        const int d = lane + 32;
        const float cc1 = cosp[ss*HD + d],      ss1 = sinp[ss*HD + d];
        const float cc2 = cosp[ss*HD + d + 40], ss2 = sinp[ss*HD + d + 40];
        a = g_q[base + d]; b2 = g_q[base + d + 40];
        qo3 = a*cc1 - b2*ss1; qo4 = b2*cc2 + a*ss2;
        a = g_k[base + d]; b2 = g_k[base + d + 40];
        ko3 = a*cc1 - b2*ss1; ko4 = b2*cc2 + a*ss2;
    }

    float qm = fmaxf(fmaxf(fabsf(qo1), fabsf(qo2)), fmaxf(fabsf(qo3), fabsf(qo4)));
    float km = fmaxf(fmaxf(fabsf(ko1), fabsf(ko2)), fmaxf(fabsf(ko3), fabsf(ko4)));
    #pragma unroll
    for (int off = 16; off >= 1; off >>= 1) {
        qm = fmaxf(qm, __shfl_xor_sync(0xffffffffu, qm, off));
        km = fmaxf(km, __shfl_xor_sync(0xffffffffu, km, off));
    }
    const float sq = (qm > 0.f) ? qm * (1.f/120.f) : 1.f;
    const float sk = (km > 0.f) ? km * (1.f/120.f) : 1.f;
    const float iq = 1.f / sq, ik = 1.f / sk;

    const size_t rb = (size_t)row * QPAD;
    auto putq = [&](int d, float v) {
        const float f = v * iq;
        const float q1 = rintf(f);
        qq1_g[rb + d] = (int8_t)(int)q1;
        qq2_g[rb + d] = (int8_t)(int)rintf(250.f * (f - q1));
    };
    auto putk = [&](int d, float v) {
        const float f = v * ik;
        const float q1 = rintf(f);
        kq1_g[rb + d] = (int8_t)(int)q1;
        kq2_g[rb + d] = (int8_t)(int)rintf(250.f * (f - q1));
    };
    putq(d0, qo1); putq(d0 + 40, qo2);
    putk(d0, ko1); putk(d0 + 40, ko2);
    if (two) {
        putq(d0 + 32, qo3); putq(d0 + 72, qo4);
        putk(d0 + 32, ko3); putk(d0 + 72, ko4);
    }
    if (lane < 16) {
        qq1_g[rb + 80 + lane] = 0; qq2_g[rb + 80 + lane] = 0;
        kq1_g[rb + 80 + lane] = 0; kq2_g[rb + 80 + lane] = 0;
    }
    if (lane == 0) { sq_g[row] = sq; sk_g[row] = sk; }
}

// ---------------------------------------------------------------------------
// V: per-(bh,d) column quantization + transpose.
// grid = 128 (bh, half). vt[bh][d][s] int8 2-digit, sv[bh*80+d] scales.
// ---------------------------------------------------------------------------
__global__ void __launch_bounds__(256) vtquant()
{
    const int bh   = blockIdx.x >> 1;
    const int half = blockIdx.x & 1;
    const int tid  = threadIdx.x;
    __shared__ uint32_t smax[80];
    __shared__ float sinv[80];
    __shared__ float stg[128 * 84];

    if (tid < 80) smax[tid] = 0u;
    __syncthreads();

    const float* vp = g_v + (size_t)bh * (SQ * HD);
    for (int i = tid; i < SQ * HD; i += 256)
        atomicMax(&smax[i % 80], __float_as_uint(fabsf(vp[i])));
    __syncthreads();

    if (tid < 80) {
        const float mx = __uint_as_float(smax[tid]);
        const float s = (mx > 0.f) ? mx * (1.f / 120.f) : 1.f;
        if (half == 0) sv_g[bh * 80 + tid] = s;
        sinv[tid] = 1.f / s;
    }
    __syncthreads();

    for (int t = half * 4; t < half * 4 + 4; t++) {
        for (int i = tid; i < 128 * 80; i += 256) {
            const int r = i / 80, c = i - r * 80;
            stg[r * 84 + c] = vp[t * 128 * 80 + i];
        }
        __syncthreads();
        for (int idx = tid; idx < 640; idx += 256) {
            const int d = idx >> 3, c = idx & 7;
            const float inv = sinv[d];
            uint32_t w1[4], w2[4];
            #pragma unroll
            for (int g2 = 0; g2 < 4; g2++) {
                uint32_t a = 0, b = 0;
                #pragma unroll
                for (int e = 0; e < 4; e++) {
                    const float f = stg[(c*16 + g2*4 + e) * 84 + d] * inv;
                    const float q = rintf(f);
                    const int i1 = (int)q;
                    const int i2 = (int)rintf(250.f * (f - q));
                    a |= (uint32_t)(i1 & 0xFF) << (8 * e);
                    b |= (uint32_t)(i2 & 0xFF) << (8 * e);
                }
                w1[g2] = a; w2[g2] = b;
            }
            const size_t dst = ((size_t)bh * 80 + d) * SQ + t * 128 + c * 16;
            *(int4*)&vt1_g[dst] = make_int4(w1[0], w1[1], w1[2], w1[3]);
            *(int4*)&vt2_g[dst] = make_int4(w2[0], w2[1], w2[2], w2[3]);
        }
        __syncthreads();
    }
}

// ===========================================================================
// Flash attention: S-phase int8 2-digit, PV int8 2-digit (P staged via smem,
// V transposed + column-scaled). CTA = (q-tile 128, bh), 8 warps.
// ===========================================================================
#define QIP 112
#define AQ1 0
#define AQ2 14336
#define PSTG 28672                       // 8 warps * 2560 (16x80 x 2 digits)
#define AKVQ 49152
#define SK1o 0
#define SK2o 7168
#define SV1o 14336                       // 80 rows(d) x 80 pitch
#define SV2o 20736
#define SSKo 27136                       // 64 floats
#define KVSTG 27392
#define ATTN_SMEM (AKVQ + 2*KVSTG)       // 103936

__global__ void __launch_bounds__(256) attn_tc()
{
    extern __shared__ char dsm_raw[];
    const uint32_t base = s2u(dsm_raw);

    const int tid = threadIdx.x;
    const int w = tid >> 5, lane = tid & 31;
    const int qt = blockIdx.x, bh = blockIdx.y;
    const int b = bh >> 4, h = bh & 15;
    const float scale = 0.11180339887498948f;  // 1/sqrt(80)

    const size_t row0 = (size_t)bh * SQ;
    const size_t qrow0 = row0 + qt * 128;

    auto ISSUE_KV = [&](int kt) {
        const uint32_t sb = base + AKVQ + (kt & 1) * KVSTG;
        const size_t kr = row0 + kt * 64;
        #pragma unroll
        for (int j = 0; j < 6; j++) {
            const int idx = tid + 256 * j;        // 0..1423 used
            if (idx < 384) {
                const int r = idx / 6, c = idx - r * 6;
                cpasync16(sb + SK1o + r * QIP + c * 16,
                          kq1_g + (kr + r) * QPAD + c * 16);
            } else if (idx < 768) {
                const int l = idx - 384, r = l / 6, c = l - r * 6;
                cpasync16(sb + SK2o + r * QIP + c * 16,
                          kq2_g + (kr + r) * QPAD + c * 16);
            } else if (idx < 1088) {
                const int l = idx - 768, r = l >> 2, c = l & 3;
                cpasync16(sb + SV1o + r * 80 + c * 16,
                          vt1_g + ((size_t)bh * 80 + r) * SQ + kt * 64 + c * 16);
            } else if (idx < 1408) {
                const int l = idx - 1088, r = l >> 2, c = l & 3;
                cpasync16(sb + SV2o + r * 80 + c * 16,
                          vt2_g + ((size_t)bh * 80 + r) * SQ + kt * 64 + c * 16);
            } else if (idx < 1424) {
                const int l = idx - 1408;
                cpasync16(sb + SSKo + l * 16, sk_g + kr + l * 4);
            }
        }
        CP_COMMIT();
    };

    // Q int8 tiles (once)
    {
        #pragma unroll
        for (int j = 0; j < 6; j++) {
            const int idx = tid + 256 * j;
            const int mat = idx / 768;
            const int rem = idx - mat * 768;
            const int r = rem / 6, c = rem - r * 6;
            cpasync16(base + (mat ? AQ2 : AQ1) + r * QIP + c * 16,
                      (mat ? qq2_g : qq1_g) + (qrow0 + r) * QPAD + c * 16);
        }
        CP_COMMIT();
    }
    ISSUE_KV(0);

    const float sq0 = sq_g[qrow0 + w*16 + (lane >> 2)];
    const float sq1 = sq_g[qrow0 + w*16 + (lane >> 2) + 8];

    // per-output-column V scales (pre-divided by 127 for P reconstruction)
    float svc0[10], svc1[10];
    #pragma unroll
    for (int nb = 0; nb < 10; nb++) {
        const int col = nb*8 + (lane & 3) * 2;
        svc0[nb] = sv_g[bh*80 + col]     * (1.f / 127.f);
        svc1[nb] = sv_g[bh*80 + col + 1] * (1.f / 127.f);
    }

    float oacc[10][4];
    #pragma unroll
    for (int i = 0; i < 10; i++)
        #pragma unroll
        for (int j = 0; j < 4; j++) oacc[i][j] = 0.f;
    float m0 = -1e30f, m1 = -1e30f, l0 = 0.f, l1 = 0.f;

    const uint32_t pw = base + PSTG + w * 2560;   // warp-private P digits

    for (int kt = 0; kt < 16; kt++) {
        if (kt + 1 < 16) { ISSUE_KV(kt + 1); CP_WAIT1(); } else { CP_WAIT0(); }
        __syncthreads();

        const uint32_t kvb = base + AKVQ + (kt & 1) * KVSTG;
        const float* skf = (const float*)(dsm_raw + AKVQ + (kt & 1) * KVSTG + SSKo);

        // ---- S = Q K^T, int8 2-digit ----
        int accP[8][4], accX[8][4];
        #pragma unroll
        for (int i = 0; i < 8; i++)
            #pragma unroll
            for (int j = 0; j < 4; j++) { accP[i][j] = 0; accX[i][j] = 0; }

        #pragma unroll
        for (int kc = 0; kc < 3; kc++) {
            uint32_t Ad1[4], Ad2[4];
            const uint32_t aoff =
                (uint32_t)((w*16 + (lane & 15)) * QIP + kc*32 + (lane >> 4) * 16);
            ldm_x4(Ad1, base + AQ1 + aoff);
            ldm_x4(Ad2, base + AQ2 + aoff);
            uint32_t Bd1[4][4], Bd2[4][4];
            #pragma unroll
            for (int g = 0; g < 4; g++) {
                const int quad = lane >> 3;
                const uint32_t boff =
                    (uint32_t)((g*16 + (quad >> 1) * 8 + (lane & 7)) * QIP
                               + kc*32 + (quad & 1) * 16);
                ldm_x4(Bd1[g], kvb + SK1o + boff);
                ldm_x4(Bd2[g], kvb + SK2o + boff);
            }
            #pragma unroll
            for (int nb = 0; nb < 8; nb++)
                mma_s8(accP[nb], Ad1, Bd1[nb>>1][(nb&1)*2], Bd1[nb>>1][(nb&1)*2+1]);
            #pragma unroll
            for (int nb = 0; nb < 8; nb++)
                mma_s8(accX[nb], Ad1, Bd2[nb>>1][(nb&1)*2], Bd2[nb>>1][(nb&1)*2+1]);
            #pragma unroll
            for (int nb = 0; nb < 8; nb++)
                mma_s8(accX[nb], Ad2, Bd1[nb>>1][(nb&1)*2], Bd1[nb>>1][(nb&1)*2+1]);
        }

        // ---- reconstruct scores + online softmax ----
        float sacc[8][4];
        #pragma unroll
        for (int nb = 0; nb < 8; nb++) {
            const int col = nb*8 + (lane & 3) * 2;
            const float k0 = skf[col] * scale, k1 = skf[col + 1] * scale;
            sacc[nb][0] = sq0 * k0 * ((float)accP[nb][0] + (float)accX[nb][0] * 0.004f);
            sacc[nb][1] = sq0 * k1 * ((float)accP[nb][1] + (float)accX[nb][1] * 0.004f);
            sacc[nb][2] = sq1 * k0 * ((float)accP[nb][2] + (float)accX[nb][2] * 0.004f);
            sacc[nb][3] = sq1 * k1 * ((float)accP[nb][3] + (float)accX[nb][3] * 0.004f);
        }

        float mx0 = -1e30f, mx1 = -1e30f;
        #pragma unroll
        for (int nb = 0; nb < 8; nb++) {
            mx0 = fmaxf(mx0, fmaxf(sacc[nb][0], sacc[nb][1]));
            mx1 = fmaxf(mx1, fmaxf(sacc[nb][2], sacc[nb][3]));
        }
        mx0 = fmaxf(mx0, __shfl_xor_sync(0xffffffffu, mx0, 1));
        mx0 = fmaxf(mx0, __shfl_xor_sync(0xffffffffu, mx0, 2));
        mx1 = fmaxf(mx1, __shfl_xor_sync(0xffffffffu, mx1, 1));
        mx1 = fmaxf(mx1, __shfl_xor_sync(0xffffffffu, mx1, 2));

        const float mn0 = fmaxf(m0, mx0), mn1 = fmaxf(m1, mx1);
        const float al0 = __expf(m0 - mn0), al1 = __expf(m1 - mn1);
        m0 = mn0; m1 = mn1;

        float rs0 = 0.f, rs1 = 0.f;
        #pragma unroll
        for (int nb = 0; nb < 8; nb++) {
            sacc[nb][0] = __expf(sacc[nb][0] - m0);
            sacc[nb][1] = __expf(sacc[nb][1] - m0);
            sacc[nb][2] = __expf(sacc[nb][2] - m1);
            sacc[nb][3] = __expf(sacc[nb][3] - m1);
            rs0 += sacc[nb][0] + sacc[nb][1];
            rs1 += sacc[nb][2] + sacc[nb][3];
        }
        rs0 += __shfl_xor_sync(0xffffffffu, rs0, 1);
        rs0 += __shfl_xor_sync(0xffffffffu, rs0, 2);
        rs1 += __shfl_xor_sync(0xffffffffu, rs1, 1);
        rs1 += __shfl_xor_sync(0xffffffffu, rs1, 2);
        l0 = l0 * al0 + rs0;
        l1 = l1 * al1 + rs1;

        #pragma unroll
        for (int nb = 0; nb < 10; nb++) {
            oacc[nb][0] *= al0; oacc[nb][1] *= al0;
            oacc[nb][2] *= al1; oacc[nb][3] *= al1;
        }

        // ---- quantize P (fixed scale 127) and stage digits to smem ----
        #pragma unroll
        for (int nb = 0; nb < 8; nb++) {
            const uint32_t a0 = pw + (uint32_t)((lane >> 2) * 80 + nb*8 + (lane & 3)*2);
            const uint32_t a1 = a0 + 8 * 80;
            float f, g; int p0, x0, p1, x1;
            f = sacc[nb][0] * 127.f; g = rintf(f); p0 = (int)g; x0 = (int)rintf(250.f*(f-g));
            f = sacc[nb][1] * 127.f; g = rintf(f); p1 = (int)g; x1 = (int)rintf(250.f*(f-g));
            st16(a0, p0, p1); st16(a0 + 1280, x0, x1);
            f = sacc[nb][2] * 127.f; g = rintf(f); p0 = (int)g; x0 = (int)rintf(250.f*(f-g));
            f = sacc[nb][3] * 127.f; g = rintf(f); p1 = (int)g; x1 = (int)rintf(250.f*(f-g));
            st16(a1, p0, p1); st16(a1 + 1280, x0, x1);
        }
        __syncwarp();

        // ---- O += P @ V^T, int8 2-digit ----
        int aP[10][4], aX[10][4];
        #pragma unroll
        for (int i = 0; i < 10; i++)
            #pragma unroll
            for (int j = 0; j < 4; j++) { aP[i][j] = 0; aX[i][j] = 0; }

        #pragma unroll
        for (int kc = 0; kc < 2; kc++) {
            uint32_t Pd1[4], Pd2[4];
            const uint32_t po = pw + (uint32_t)((lane & 15) * 80 + kc*32 + (lane >> 4) * 16);
            ldm_x4(Pd1, po);
            ldm_x4(Pd2, po + 1280);
            uint32_t Vd1[5][4], Vd2[5][4];
            #pragma unroll
            for (int vg = 0; vg < 5; vg++) {
                const int quad = lane >> 3;
                const uint32_t vo =
                    (uint32_t)((vg*16 + (quad >> 1) * 8 + (lane & 7)) * 80
                               + kc*32 + (quad & 1) * 16);
                ldm_x4(Vd1[vg], kvb + SV1o + vo);
                ldm_x4(Vd2[vg], kvb + SV2o + vo);
            }
            #pragma unroll
            for (int nb = 0; nb < 10; nb++)
                mma_s8(aP[nb], Pd1, Vd1[nb>>1][(nb&1)*2], Vd1[nb>>1][(nb&1)*2+1]);
            #pragma unroll
            for (int nb = 0; nb < 10; nb++)
                mma_s8(aX[nb], Pd1, Vd2[nb>>1][(nb&1)*2], Vd2[nb>>1][(nb&1)*2+1]);
            #pragma unroll
            for (int nb = 0; nb < 10; nb++)
                mma_s8(aX[nb], Pd2, Vd1[nb>>1][(nb&1)*2], Vd1[nb>>1][(nb&1)*2+1]);
        }

        #pragma unroll
        for (int nb = 0; nb < 10; nb++) {
            oacc[nb][0] += svc0[nb] * ((float)aP[nb][0] + 0.004f * (float)aX[nb][0]);
            oacc[nb][1] += svc1[nb] * ((float)aP[nb][1] + 0.004f * (float)aX[nb][1]);
            oacc[nb][2] += svc0[nb] * ((float)aP[nb][2] + 0.004f * (float)aX[nb][2]);
            oacc[nb][3] += svc1[nb] * ((float)aP[nb][3] + 0.004f * (float)aX[nb][3]);
        }
        __syncthreads();
    }

    // ---- finalize ----
    const float inv0 = 1.f / l0, inv1 = 1.f / l1;
    const int s0 = qt*128 + w*16 + (lane >> 2);
    const int s1 = s0 + 8;
    #pragma unroll
    for (int nb = 0; nb < 10; nb++) {
        const int d = nb*8 + (lane & 3) * 2;
        {
            float2 v; v.x = oacc[nb][0] * inv0; v.y = oacc[nb][1] * inv0;
            *(float2*)&g_ctx[((size_t)b * SQ + s0) * DM + h * HD + d] = v;
        }
        {
            float2 v; v.x = oacc[nb][2] * inv1; v.y = oacc[nb][3] * inv1;
            *(float2*)&g_ctx[((size_t)b * SQ + s1) * DM + h * HD + d] = v;
        }
    }
}

// ---------------------------------------------------------------------------
extern "C" void kernel_launch(void* const* d_in, const int* in_sizes, int n_in,
                              void* d_out, int out_size)
{
    (void)in_sizes; (void)n_in; (void)out_size;
    const float* x     = (const float*)d_in[0];
    const float* cosp  = (const float*)d_in[1];
    const float* sinp  = (const float*)d_in[2];
    const float* Wqkv  = (const float*)d_in[3];
    const float* bqkv  = (const float*)d_in[4];
    const float* Wproj = (const float*)d_in[5];
    const float* bproj = (const float*)d_in[6];
    float* out = (float*)d_out;

    cudaFuncSetAttribute(gemm_i8<false>,
                         cudaFuncAttributeMaxDynamicSharedMemorySize, IGEMM_DSMEM);
    cudaFuncSetAttribute(gemm_i8<true>,
                         cudaFuncAttributeMaxDynamicSharedMemorySize, IGEMM_DSMEM);
    cudaFuncSetAttribute(attn_tc,
                         cudaFuncAttributeMaxDynamicSharedMemorySize, ATTN_SMEM);

    int8_t *xq1, *xq2, *wq1, *wq2;
    float *sax, *sbw, *ctx;
    cudaGetSymbolAddress((void**)&xq1, xq1_g);
    cudaGetSymbolAddress((void**)&xq2, xq2_g);
    cudaGetSymbolAddress((void**)&wq1, wq1_g);
    cudaGetSymbolAddress((void**)&wq2, wq2_g);
    cudaGetSymbolAddress((void**)&sax, sax_g);
    cudaGetSymbolAddress((void**)&sbw, sbw_g);
    cudaGetSymbolAddress((void**)&ctx, g_ctx);

    // 0) quantize x, Wqkv
    quant_kernel<<<MTOT, 128>>>(x, xq1, xq2, sax);
    quant_kernel<<<NQKV, 128>>>(Wqkv, wq1, wq2, sbw);
    // 1) QKV GEMM (int8): q,k,v fp32 head-major
    gemm_i8<false><<<dim3(NQKV/64, MTOT/128), 256, IGEMM_DSMEM>>>(
        xq1, xq2, wq1, wq2, sax, sbw, bqkv, nullptr);
    // 2) RoPE + q/k int8 quant; V column-quant + transpose
    rope_quant<<<NROWS/8, 256>>>(cosp, sinp);
    vtquant<<<NB*NH*2, 256>>>();
    // 3) attention (int8 S + int8 PV) -> fp32 ctx
    attn_tc<<<dim3(SQ/128, NB*NH), 256, ATTN_SMEM>>>();
    // 4) re-quantize ctx and Wproj (reusing digit buffers)
    quant_kernel<<<MTOT, 128>>>(ctx, xq1, xq2, sax);
    quant_kernel<<<DM, 128>>>(Wproj, wq1, wq2, sbw);
    // 5) output projection (int8) -> d_out
    gemm_i8<true><<<dim3(DM/64, MTOT/128), 256, IGEMM_DSMEM>>>(
        xq1, xq2, wq1, wq2, sax, sbw, bproj, out);
}

// round 12
// speedup vs baseline: 1.1427x; 1.1427x over previous
#include <cuda_runtime.h>
#include <cuda_bf16.h>
#include <cstdint>

#define NB 4
#define SQ 1024
#define DM 1280
#define NH 16
#define HD 80
#define MTOT (NB*SQ)      // 4096
#define NQKV (3*DM)       // 3840
#define NROWS (NB*NH*SQ)  // 65536
#define QPAD 96           // int8 q/k rows padded 80 -> 96

// ---------------------------------------------------------------------------
// Scratch (__device__ globals; allocation-free rule)
// ---------------------------------------------------------------------------
__device__ float g_q[NROWS*HD];
__device__ float g_k[NROWS*HD];
__device__ float g_ctx[MTOT*DM];

// int8 2-digit operands (xq*/sax reused for ctx; wq*/sbw reused for Wproj)
__device__ int8_t xq1_g[MTOT*DM],  xq2_g[MTOT*DM];
__device__ int8_t wq1_g[NQKV*DM],  wq2_g[NQKV*DM];
__device__ float  sax_g[MTOT];
__device__ float  sbw_g[NQKV];

// int8 2-digit rotated q/k + per-row scales
__device__ int8_t qq1_g[NROWS*QPAD], qq2_g[NROWS*QPAD];
__device__ int8_t kq1_g[NROWS*QPAD], kq2_g[NROWS*QPAD];
__device__ float  sq_g[NROWS], sk_g[NROWS];

// bf16 hi/lo V (PV stays bf16)
__device__ __nv_bfloat16 vh_g[NROWS*HD], vl_g[NROWS*HD];

// ---------------------------------------------------------------------------
// helpers
// ---------------------------------------------------------------------------
__device__ __forceinline__ uint32_t s2u(const void* p) {
    uint32_t a;
    asm("{ .reg .u64 t; cvta.to.shared.u64 t, %1; cvt.u32.u64 %0, t; }"
        : "=r"(a) : "l"(p));
    return a;
}
__device__ __forceinline__ void ldm_x4(uint32_t* r, uint32_t addr) {
    asm volatile("ldmatrix.sync.aligned.m8n8.x4.shared.b16 {%0,%1,%2,%3}, [%4];"
        : "=r"(r[0]), "=r"(r[1]), "=r"(r[2]), "=r"(r[3]) : "r"(addr));
}
__device__ __forceinline__ void ldm_x4_t(uint32_t* r, uint32_t addr) {
    asm volatile("ldmatrix.sync.aligned.m8n8.x4.trans.shared.b16 {%0,%1,%2,%3}, [%4];"
        : "=r"(r[0]), "=r"(r[1]), "=r"(r[2]), "=r"(r[3]) : "r"(addr));
}
__device__ __forceinline__ void mma16816(float* c, const uint32_t* a,
                                         uint32_t b0, uint32_t b1) {
    asm volatile(
        "mma.sync.aligned.m16n8k16.row.col.f32.bf16.bf16.f32 "
        "{%0,%1,%2,%3}, {%4,%5,%6,%7}, {%8,%9}, {%0,%1,%2,%3};"
        : "+f"(c[0]), "+f"(c[1]), "+f"(c[2]), "+f"(c[3])
        : "r"(a[0]), "r"(a[1]), "r"(a[2]), "r"(a[3]), "r"(b0), "r"(b1));
}
__device__ __forceinline__ void mma_s8(int* c, const uint32_t* a,
                                       uint32_t b0, uint32_t b1) {
    asm volatile(
        "mma.sync.aligned.m16n8k32.row.col.s32.s8.s8.s32 "
        "{%0,%1,%2,%3}, {%4,%5,%6,%7}, {%8,%9}, {%0,%1,%2,%3};"
        : "+r"(c[0]), "+r"(c[1]), "+r"(c[2]), "+r"(c[3])
        : "r"(a[0]), "r"(a[1]), "r"(a[2]), "r"(a[3]), "r"(b0), "r"(b1));
}
__device__ __forceinline__ uint32_t packbf(float a, float b) {
    __nv_bfloat162 t = __floats2bfloat162_rn(a, b);
    return *reinterpret_cast<uint32_t*>(&t);
}
__device__ __forceinline__ void cpasync16(uint32_t dst, const void* src) {
    asm volatile("cp.async.ca.shared.global [%0], [%1], 16;"
        :: "r"(dst), "l"(src) : "memory");
}
#define CP_COMMIT() asm volatile("cp.async.commit_group;" ::: "memory")
#define CP_WAIT0()  asm volatile("cp.async.wait_group 0;" ::: "memory")
#define CP_WAIT1()  asm volatile("cp.async.wait_group 1;" ::: "memory")

// ---------------------------------------------------------------------------
// fp32 -> int8 2-digit row quantization: v = s*(d1 + d2/250), s = rowmax/120.
// ---------------------------------------------------------------------------
__global__ void __launch_bounds__(128) quant_kernel(
    const float* __restrict__ src, int8_t* __restrict__ d1,
    int8_t* __restrict__ d2, float* __restrict__ scale)
{
    const int row = blockIdx.x;
    const int tid = threadIdx.x;
    const float* p = src + (size_t)row * DM;
    float mx = 0.f;
    for (int i = tid; i < DM; i += 128) mx = fmaxf(mx, fabsf(p[i]));
    #pragma unroll
    for (int off = 16; off >= 1; off >>= 1)
        mx = fmaxf(mx, __shfl_xor_sync(0xffffffffu, mx, off));
    __shared__ float smx[4];
    if ((tid & 31) == 0) smx[tid >> 5] = mx;
    __syncthreads();
    mx = fmaxf(fmaxf(smx[0], smx[1]), fmaxf(smx[2], smx[3]));
    const float s = (mx > 0.f) ? mx * (1.f / 120.f) : 1.f;
    const float inv = 1.f / s;
    for (int i = tid; i < DM; i += 128) {
        const float f  = p[i] * inv;
        const float q1 = rintf(f);
        const float q2 = rintf(250.f * (f - q1));
        d1[(size_t)row * DM + i] = (int8_t)(int)q1;
        d2[(size_t)row * DM + i] = (int8_t)(int)q2;
    }
    if (tid == 0) scale[row] = s;
}

// ===========================================================================
// int8 2-digit GEMM core: C = sa[m]*sb[n]*(P + X/250) + bias[n].
// CTA 128(M)x64(N), 256 thr, 8 warps of 32x32, K-stage 128 int8, 2-stage.
// PROJ=false: QKV (scatter q,k fp32 + v bf16 hi/lo). PROJ=true: dense out.
// ===========================================================================
#define IK 128
#define IPITCH 144
#define IOFF_A2 (128*IPITCH)
#define IOFF_B1 (2*128*IPITCH)
#define IOFF_B2 (IOFF_B1 + 64*IPITCH)
#define ISTAGE (IOFF_B2 + 64*IPITCH)
#define IGEMM_DSMEM (2*ISTAGE)         // 110592

template<bool PROJ>
__global__ void __launch_bounds__(256, 2) gemm_i8(
    const int8_t* __restrict__ A1, const int8_t* __restrict__ A2,
    const int8_t* __restrict__ B1, const int8_t* __restrict__ B2,
    const float* __restrict__ sa_v, const float* __restrict__ sb_v,
    const float* __restrict__ bias, float* __restrict__ Cout)
{
    extern __shared__ char dsm_raw[];
    const uint32_t base = s2u(dsm_raw);

    const int tid  = threadIdx.x;
    const int wid  = tid >> 5, lane = tid & 31;
    const int bx = blockIdx.x, by = blockIdx.y;
    const int wm = wid >> 1, wn = wid & 1;    // warp tile 32(M) x 32(N)

    const int8_t* a1p = A1 + (size_t)(by * 128) * DM;
    const int8_t* a2p = A2 + (size_t)(by * 128) * DM;
    const int8_t* b1p = B1 + (size_t)(bx * 64) * DM;
    const int8_t* b2p = B2 + (size_t)(bx * 64) * DM;

    auto ISSUE = [&](int it) {
        const uint32_t sb = base + (it & 1) * ISTAGE;
        const int kof = it * IK;
        #pragma unroll
        for (int j = 0; j < 12; j++) {
            const int idx = tid + 256 * j;
            int local; uint32_t moff; const int8_t* srcp;
            if (j < 4)       { local = idx;        moff = 0;       srcp = a1p; }
            else if (j < 8)  { local = idx - 1024; moff = IOFF_A2; srcp = a2p; }
            else if (j < 10) { local = idx - 2048; moff = IOFF_B1; srcp = b1p; }
            else             { local = idx - 2560; moff = IOFF_B2; srcp = b2p; }
            const int r = local >> 3, c = local & 7;
            cpasync16(sb + moff + r * IPITCH + c * 16,
                      srcp + (size_t)r * DM + kof + c * 16);
        }
        CP_COMMIT();
    };

    int accP[2][4][4], accX[2][4][4];
    #pragma unroll
    for (int i = 0; i < 2; i++)
        #pragma unroll
        for (int j = 0; j < 4; j++)
            #pragma unroll
            for (int q = 0; q < 4; q++) { accP[i][j][q] = 0; accX[i][j][q] = 0; }

    ISSUE(0); ISSUE(1);

    const int NITI = DM / IK;
    for (int it = 0; it < NITI; ++it) {
        if (it == NITI - 1) { CP_WAIT0(); } else { CP_WAIT1(); }
        __syncthreads();

        const uint32_t sb = base + (it & 1) * ISTAGE;
        #pragma unroll
        for (int kc = 0; kc < 4; kc++) {
            uint32_t Ad1[2][4], Ad2[2][4];
            #pragma unroll
            for (int mf = 0; mf < 2; mf++) {
                const uint32_t aoff =
                    (uint32_t)((wm*32 + mf*16 + (lane & 15)) * IPITCH
                               + kc*32 + (lane >> 4) * 16);
                ldm_x4(Ad1[mf], sb + aoff);
                ldm_x4(Ad2[mf], sb + IOFF_A2 + aoff);
            }
            uint32_t Bd1[2][4], Bd2[2][4];
            #pragma unroll
            for (int g = 0; g < 2; g++) {
                const int quad = lane >> 3;
                const uint32_t boff =
                    (uint32_t)((wn*32 + g*16 + (quad >> 1) * 8 + (lane & 7)) * IPITCH
                               + kc*32 + (quad & 1) * 16);
                ldm_x4(Bd1[g], sb + IOFF_B1 + boff);
                ldm_x4(Bd2[g], sb + IOFF_B2 + boff);
            }
            #pragma unroll
            for (int mf = 0; mf < 2; mf++)
                #pragma unroll
                for (int nb = 0; nb < 4; nb++)
                    mma_s8(accP[mf][nb], Ad1[mf], Bd1[nb>>1][(nb&1)*2], Bd1[nb>>1][(nb&1)*2+1]);
            #pragma unroll
            for (int mf = 0; mf < 2; mf++)
                #pragma unroll
                for (int nb = 0; nb < 4; nb++)
                    mma_s8(accX[mf][nb], Ad1[mf], Bd2[nb>>1][(nb&1)*2], Bd2[nb>>1][(nb&1)*2+1]);
            #pragma unroll
            for (int mf = 0; mf < 2; mf++)
                #pragma unroll
                for (int nb = 0; nb < 4; nb++)
                    mma_s8(accX[mf][nb], Ad2[mf], Bd1[nb>>1][(nb&1)*2], Bd1[nb>>1][(nb&1)*2+1]);
        }
        __syncthreads();
        if (it + 2 < NITI) ISSUE(it + 2);
    }

    #pragma unroll
    for (int mf = 0; mf < 2; mf++)
        #pragma unroll
        for (int nb = 0; nb < 4; nb++)
            #pragma unroll
            for (int ci = 0; ci < 2; ci++) {
                const int m = by*128 + wm*32 + mf*16 + (lane >> 2) + ci*8;
                const int n = bx*64 + wn*32 + nb*8 + (lane & 3) * 2;
                const float sa = sa_v[m];
                float2 v;
                v.x = sa * sb_v[n]   * ((float)accP[mf][nb][2*ci+0]
                        + (float)accX[mf][nb][2*ci+0] * 0.004f) + bias[n];
                v.y = sa * sb_v[n+1] * ((float)accP[mf][nb][2*ci+1]
                        + (float)accX[mf][nb][2*ci+1] * 0.004f) + bias[n+1];
                if (PROJ) {
                    *(float2*)&Cout[(size_t)m * DM + n] = v;
                } else {
                    const int sel = n / DM;
                    const int r2  = n - sel * DM;
                    const int h   = r2 / HD;
                    const int dd  = r2 - h * HD;
                    const int bb  = m >> 10;
                    const int ss  = m & (SQ - 1);
                    const size_t di = (((size_t)bb * NH + h) * SQ + ss) * HD + dd;
                    if (sel == 0)      *(float2*)&g_q[di] = v;
                    else if (sel == 1) *(float2*)&g_k[di] = v;
                    else {
                        __nv_bfloat16 h0 = __float2bfloat16_rn(v.x);
                        __nv_bfloat16 h1 = __float2bfloat16_rn(v.y);
                        *(__nv_bfloat162*)&vh_g[di] = __nv_bfloat162(h0, h1);
                        *(__nv_bfloat162*)&vl_g[di] = __floats2bfloat162_rn(
                            v.x - __bfloat162float(h0), v.y - __bfloat162float(h1));
                    }
                }
            }
}

// ---------------------------------------------------------------------------
// RoPE + int8 2-digit quantization. One warp per (b,h,s) row of 80.
// ---------------------------------------------------------------------------
__global__ void __launch_bounds__(256) rope_quant(
    const float* __restrict__ cosp, const float* __restrict__ sinp)
{
    const int row  = (blockIdx.x << 3) + (threadIdx.x >> 5);   // < NROWS
    const int lane = threadIdx.x & 31;
    const int ss   = row & (SQ - 1);
    const size_t base = (size_t)row * HD;

    const int d0 = lane;                 // 0..31 (< 40)
    const bool two = lane < 8;           // second pair d = lane+32 (< 40)

    const float c1 = cosp[ss*HD + d0],      s1 = sinp[ss*HD + d0];
    const float c2 = cosp[ss*HD + d0 + 40], s2 = sinp[ss*HD + d0 + 40];
    float a, b2;

    a = g_q[base + d0]; b2 = g_q[base + d0 + 40];
    float qo1 = a*c1 - b2*s1, qo2 = b2*c2 + a*s2;
    a = g_k[base + d0]; b2 = g_k[base + d0 + 40];
    float ko1 = a*c1 - b2*s1, ko2 = b2*c2 + a*s2;

    float qo3 = 0.f, qo4 = 0.f, ko3 = 0.f, ko4 = 0.f;
    if (two) {
        const int d = lane + 32;
        const float cc1 = cosp[ss*HD + d],      ss1 = sinp[ss*HD + d];
        const float cc2 = cosp[ss*HD + d + 40], ss2 = sinp[ss*HD + d + 40];
        a = g_q[base + d]; b2 = g_q[base + d + 40];
        qo3 = a*cc1 - b2*ss1; qo4 = b2*cc2 + a*ss2;
        a = g_k[base + d]; b2 = g_k[base + d + 40];
        ko3 = a*cc1 - b2*ss1; ko4 = b2*cc2 + a*ss2;
    }

    float qm = fmaxf(fmaxf(fabsf(qo1), fabsf(qo2)), fmaxf(fabsf(qo3), fabsf(qo4)));
    float km = fmaxf(fmaxf(fabsf(ko1), fabsf(ko2)), fmaxf(fabsf(ko3), fabsf(ko4)));
    #pragma unroll
    for (int off = 16; off >= 1; off >>= 1) {
        qm = fmaxf(qm, __shfl_xor_sync(0xffffffffu, qm, off));
        km = fmaxf(km, __shfl_xor_sync(0xffffffffu, km, off));
    }
    const float sq = (qm > 0.f) ? qm * (1.f/120.f) : 1.f;
    const float sk = (km > 0.f) ? km * (1.f/120.f) : 1.f;
    const float iq = 1.f / sq, ik = 1.f / sk;

    const size_t rb = (size_t)row * QPAD;
    auto putq = [&](int d, float v) {
        const float f = v * iq;
        const float q1 = rintf(f);
        qq1_g[rb + d] = (int8_t)(int)q1;
        qq2_g[rb + d] = (int8_t)(int)rintf(250.f * (f - q1));
    };
    auto putk = [&](int d, float v) {
        const float f = v * ik;
        const float q1 = rintf(f);
        kq1_g[rb + d] = (int8_t)(int)q1;
        kq2_g[rb + d] = (int8_t)(int)rintf(250.f * (f - q1));
    };
    putq(d0, qo1); putq(d0 + 40, qo2);
    putk(d0, ko1); putk(d0 + 40, ko2);
    if (two) {
        putq(d0 + 32, qo3); putq(d0 + 72, qo4);
        putk(d0 + 32, ko3); putk(d0 + 72, ko4);
    }
    if (lane < 16) {  // zero pad cols 80..95
        qq1_g[rb + 80 + lane] = 0; qq2_g[rb + 80 + lane] = 0;
        kq1_g[rb + 80 + lane] = 0; kq2_g[rb + 80 + lane] = 0;
    }
    if (lane == 0) { sq_g[row] = sq; sk_g[row] = sk; }
}

// ===========================================================================
// Flash attention: S-phase int8 2-digit (k32), PV bf16 3-pass.
// CTA = (q-tile 128 rows, bh), 8 warps. Double-buffered K/V.
// __launch_bounds__(256,2): force regs<=128 so 2 CTAs co-reside per SM.
// ===========================================================================
#define QIP 112                          // int8 row pitch in smem (96 + 16)
#define AQ1 0                            // QI1: 128*112 = 14336
#define AQ2 14336
#define AKVQ 28672
#define SK1o 0
#define SK2o 7168
#define SVHo 14336
#define SVLo 25600
#define SSKo 36864                       // 64 floats
#define KVSTG 37120
#define ATTN_SMEM (AKVQ + 2*KVSTG)       // 102912
#define APITCH 176                       // bf16 V row pitch

__global__ void __launch_bounds__(256, 2) attn_tc()
{
    extern __shared__ char dsm_raw[];
    const uint32_t base = s2u(dsm_raw);

    const int tid = threadIdx.x;
    const int w = tid >> 5, lane = tid & 31;
    const int qt = blockIdx.x, bh = blockIdx.y;
    const int b = bh >> 4, h = bh & 15;
    const float scale = 0.11180339887498948f;  // 1/sqrt(80)

    const size_t row0 = (size_t)bh * SQ;
    const size_t qrow0 = row0 + qt * 128;

    auto ISSUE_KV = [&](int kt) {
        const uint32_t sb = base + AKVQ + (kt & 1) * KVSTG;
        const size_t kr = row0 + kt * 64;
        #pragma unroll
        for (int j = 0; j < 9; j++) {
            const int idx = tid + 256 * j;        // 0..2063 used
            if (idx < 384) {
                const int r = idx / 6, c = idx - r * 6;
                cpasync16(sb + SK1o + r * QIP + c * 16,
                          kq1_g + (kr + r) * QPAD + c * 16);
            } else if (idx < 768) {
                const int l = idx - 384, r = l / 6, c = l - r * 6;
                cpasync16(sb + SK2o + r * QIP + c * 16,
                          kq2_g + (kr + r) * QPAD + c * 16);
            } else if (idx < 1408) {
                const int l = idx - 768, r = l / 10, c = l - r * 10;
                cpasync16(sb + SVHo + r * APITCH + c * 16,
                          vh_g + (kr + r) * HD + c * 8);
            } else if (idx < 2048) {
                const int l = idx - 1408, r = l / 10, c = l - r * 10;
                cpasync16(sb + SVLo + r * APITCH + c * 16,
                          vl_g + (kr + r) * HD + c * 8);
            } else if (idx < 2064) {
                const int l = idx - 2048;
                cpasync16(sb + SSKo + l * 16, sk_g + kr + l * 4);
            }
        }
        CP_COMMIT();
    };

    // Q int8 tiles (once): 128 rows x 6 chunks x 2 mats = 1536
    {
        #pragma unroll
        for (int j = 0; j < 6; j++) {
            const int idx = tid + 256 * j;
            const int mat = idx / 768;
            const int rem = idx - mat * 768;
            const int r = rem / 6, c = rem - r * 6;
            cpasync16(base + (mat ? AQ2 : AQ1) + r * QIP + c * 16,
                      (mat ? qq2_g : qq1_g) + (qrow0 + r) * QPAD + c * 16);
        }
        CP_COMMIT();
    }
    ISSUE_KV(0);

    const float sq0 = sq_g[qrow0 + w*16 + (lane >> 2)];
    const float sq1 = sq_g[qrow0 + w*16 + (lane >> 2) + 8];

    float oacc[10][4];
    #pragma unroll
    for (int i = 0; i < 10; i++)
        #pragma unroll
        for (int j = 0; j < 4; j++) oacc[i][j] = 0.f;
    float m0 = -1e30f, m1 = -1e30f, l0 = 0.f, l1 = 0.f;

    for (int kt = 0; kt < 16; kt++) {
        if (kt + 1 < 16) { ISSUE_KV(kt + 1); CP_WAIT1(); } else { CP_WAIT0(); }
        __syncthreads();

        const uint32_t kvb = base + AKVQ + (kt & 1) * KVSTG;
        const float* skf = (const float*)(dsm_raw + AKVQ + (kt & 1) * KVSTG + SSKo);

        // ---- S = Q K^T, int8 2-digit (3 k-chunks x 3 passes) ----
        int accP[8][4], accX[8][4];
        #pragma unroll
        for (int i = 0; i < 8; i++)
            #pragma unroll
            for (int j = 0; j < 4; j++) { accP[i][j] = 0; accX[i][j] = 0; }

        #pragma unroll
        for (int kc = 0; kc < 3; kc++) {
            uint32_t Ad1[4], Ad2[4];
            const uint32_t aoff =
                (uint32_t)((w*16 + (lane & 15)) * QIP + kc*32 + (lane >> 4) * 16);
            ldm_x4(Ad1, base + AQ1 + aoff);
            ldm_x4(Ad2, base + AQ2 + aoff);
            uint32_t Bd1[4][4], Bd2[4][4];
            #pragma unroll
            for (int g = 0; g < 4; g++) {
                const int quad = lane >> 3;
                const uint32_t boff =
                    (uint32_t)((g*16 + (quad >> 1) * 8 + (lane & 7)) * QIP
                               + kc*32 + (quad & 1) * 16);
                ldm_x4(Bd1[g], kvb + SK1o + boff);
                ldm_x4(Bd2[g], kvb + SK2o + boff);
            }
            #pragma unroll
            for (int nb = 0; nb < 8; nb++)
                mma_s8(accP[nb], Ad1, Bd1[nb>>1][(nb&1)*2], Bd1[nb>>1][(nb&1)*2+1]);
            #pragma unroll
            for (int nb = 0; nb < 8; nb++)
                mma_s8(accX[nb], Ad1, Bd2[nb>>1][(nb&1)*2], Bd2[nb>>1][(nb&1)*2+1]);
            #pragma unroll
            for (int nb = 0; nb < 8; nb++)
                mma_s8(accX[nb], Ad2, Bd1[nb>>1][(nb&1)*2], Bd1[nb>>1][(nb&1)*2+1]);
        }

        // ---- reconstruct scores + online softmax ----
        float sacc[8][4];
        #pragma unroll
        for (int nb = 0; nb < 8; nb++) {
            const int col = nb*8 + (lane & 3) * 2;
            const float k0 = skf[col] * scale, k1 = skf[col + 1] * scale;
            sacc[nb][0] = sq0 * k0 * ((float)accP[nb][0] + (float)accX[nb][0] * 0.004f);
            sacc[nb][1] = sq0 * k1 * ((float)accP[nb][1] + (float)accX[nb][1] * 0.004f);
            sacc[nb][2] = sq1 * k0 * ((float)accP[nb][2] + (float)accX[nb][2] * 0.004f);
            sacc[nb][3] = sq1 * k1 * ((float)accP[nb][3] + (float)accX[nb][3] * 0.004f);
        }

        float mx0 = -1e30f, mx1 = -1e30f;
        #pragma unroll
        for (int nb = 0; nb < 8; nb++) {
            mx0 = fmaxf(mx0, fmaxf(sacc[nb][0], sacc[nb][1]));
            mx1 = fmaxf(mx1, fmaxf(sacc[nb][2], sacc[nb][3]));
        }
        mx0 = fmaxf(mx0, __shfl_xor_sync(0xffffffffu, mx0, 1));
        mx0 = fmaxf(mx0, __shfl_xor_sync(0xffffffffu, mx0, 2));
        mx1 = fmaxf(mx1, __shfl_xor_sync(0xffffffffu, mx1, 1));
        mx1 = fmaxf(mx1, __shfl_xor_sync(0xffffffffu, mx1, 2));

        const float mn0 = fmaxf(m0, mx0), mn1 = fmaxf(m1, mx1);
        const float al0 = __expf(m0 - mn0), al1 = __expf(m1 - mn1);
        m0 = mn0; m1 = mn1;

        float rs0 = 0.f, rs1 = 0.f;
        #pragma unroll
        for (int nb = 0; nb < 8; nb++) {
            sacc[nb][0] = __expf(sacc[nb][0] - m0);
            sacc[nb][1] = __expf(sacc[nb][1] - m0);
            sacc[nb][2] = __expf(sacc[nb][2] - m1);
            sacc[nb][3] = __expf(sacc[nb][3] - m1);
            rs0 += sacc[nb][0] + sacc[nb][1];
            rs1 += sacc[nb][2] + sacc[nb][3];
        }
        rs0 += __shfl_xor_sync(0xffffffffu, rs0, 1);
        rs0 += __shfl_xor_sync(0xffffffffu, rs0, 2);
        rs1 += __shfl_xor_sync(0xffffffffu, rs1, 1);
        rs1 += __shfl_xor_sync(0xffffffffu, rs1, 2);
        l0 = l0 * al0 + rs0;
        l1 = l1 * al1 + rs1;

        #pragma unroll
        for (int nb = 0; nb < 10; nb++) {
            oacc[nb][0] *= al0; oacc[nb][1] *= al0;
            oacc[nb][2] *= al1; oacc[nb][3] *= al1;
        }

        // ---- O += P @ V, bf16 3-pass ----
        #pragma unroll
        for (int kc = 0; kc < 4; kc++) {
            uint32_t Pa_h[4], Pa_l[4];
            #pragma unroll
            for (int half2i = 0; half2i < 2; half2i++) {
                const int nb = 2*kc + half2i;
                float f0 = sacc[nb][0], f1 = sacc[nb][1];
                float f2 = sacc[nb][2], f3 = sacc[nb][3];
                float h0 = __bfloat162float(__float2bfloat16_rn(f0));
                float h1 = __bfloat162float(__float2bfloat16_rn(f1));
                float h2 = __bfloat162float(__float2bfloat16_rn(f2));
                float h3 = __bfloat162float(__float2bfloat16_rn(f3));
                Pa_h[2*half2i+0] = packbf(h0, h1);
                Pa_h[2*half2i+1] = packbf(h2, h3);
                Pa_l[2*half2i+0] = packbf(f0 - h0, f1 - h1);
                Pa_l[2*half2i+1] = packbf(f2 - h2, f3 - h3);
            }
            uint32_t Vh4[5][4], Vl4[5][4];
            #pragma unroll
            for (int vg = 0; vg < 5; vg++) {
                const int vrow = kc*16 + ((lane >> 3) & 1) * 8 + (lane & 7);
                const int vcol = vg*16 + (lane >> 4) * 8;
                const uint32_t voff = (uint32_t)(vrow * APITCH + vcol * 2);
                ldm_x4_t(Vh4[vg], kvb + SVHo + voff);
                ldm_x4_t(Vl4[vg], kvb + SVLo + voff);
            }
            #pragma unroll
            for (int vg = 0; vg < 5; vg++)
                #pragma unroll
                for (int hh = 0; hh < 2; hh++)
                    mma16816(oacc[vg*2+hh], Pa_h, Vh4[vg][2*hh], Vh4[vg][2*hh+1]);
            #pragma unroll
            for (int vg = 0; vg < 5; vg++)
                #pragma unroll
                for (int hh = 0; hh < 2; hh++)
                    mma16816(oacc[vg*2+hh], Pa_l, Vh4[vg][2*hh], Vh4[vg][2*hh+1]);
            #pragma unroll
            for (int vg = 0; vg < 5; vg++)
                #pragma unroll
                for (int hh = 0; hh < 2; hh++)
                    mma16816(oacc[vg*2+hh], Pa_h, Vl4[vg][2*hh], Vl4[vg][2*hh+1]);
        }
        __syncthreads();
    }

    // ---- finalize: normalize, write fp32 ctx ----
    const float inv0 = 1.f / l0, inv1 = 1.f / l1;
    const int s0 = qt*128 + w*16 + (lane >> 2);
    const int s1 = s0 + 8;
    #pragma unroll
    for (int nb = 0; nb < 10; nb++) {
        const int d = nb*8 + (lane & 3) * 2;
        {
            float2 v; v.x = oacc[nb][0] * inv0; v.y = oacc[nb][1] * inv0;
            *(float2*)&g_ctx[((size_t)b * SQ + s0) * DM + h * HD + d] = v;
        }
        {
            float2 v; v.x = oacc[nb][2] * inv1; v.y = oacc[nb][3] * inv1;
            *(float2*)&g_ctx[((size_t)b * SQ + s1) * DM + h * HD + d] = v;
        }
    }
}

// ---------------------------------------------------------------------------
extern "C" void kernel_launch(void* const* d_in, const int* in_sizes, int n_in,
                              void* d_out, int out_size)
{
    (void)in_sizes; (void)n_in; (void)out_size;
    const float* x     = (const float*)d_in[0];
    const float* cosp  = (const float*)d_in[1];
    const float* sinp  = (const float*)d_in[2];
    const float* Wqkv  = (const float*)d_in[3];
    const float* bqkv  = (const float*)d_in[4];
    const float* Wproj = (const float*)d_in[5];
    const float* bproj = (const float*)d_in[6];
    float* out = (float*)d_out;

    cudaFuncSetAttribute(gemm_i8<false>,
                         cudaFuncAttributeMaxDynamicSharedMemorySize, IGEMM_DSMEM);
    cudaFuncSetAttribute(gemm_i8<true>,
                         cudaFuncAttributeMaxDynamicSharedMemorySize, IGEMM_DSMEM);
    cudaFuncSetAttribute(attn_tc,
                         cudaFuncAttributeMaxDynamicSharedMemorySize, ATTN_SMEM);

    int8_t *xq1, *xq2, *wq1, *wq2;
    float *sax, *sbw, *ctx;
    cudaGetSymbolAddress((void**)&xq1, xq1_g);
    cudaGetSymbolAddress((void**)&xq2, xq2_g);
    cudaGetSymbolAddress((void**)&wq1, wq1_g);
    cudaGetSymbolAddress((void**)&wq2, wq2_g);
    cudaGetSymbolAddress((void**)&sax, sax_g);
    cudaGetSymbolAddress((void**)&sbw, sbw_g);
    cudaGetSymbolAddress((void**)&ctx, g_ctx);

    // 0) quantize x, Wqkv
    quant_kernel<<<MTOT, 128>>>(x, xq1, xq2, sax);
    quant_kernel<<<NQKV, 128>>>(Wqkv, wq1, wq2, sbw);
    // 1) QKV GEMM (int8): q,k fp32 head-major + v bf16 hi/lo
    gemm_i8<false><<<dim3(NQKV/64, MTOT/128), 256, IGEMM_DSMEM>>>(
        xq1, xq2, wq1, wq2, sax, sbw, bqkv, nullptr);
    // 2) RoPE + int8 quant -> qq/kq + scales
    rope_quant<<<NROWS/8, 256>>>(cosp, sinp);
    // 3) attention (int8 S, bf16 PV) -> fp32 ctx
    attn_tc<<<dim3(SQ/128, NB*NH), 256, ATTN_SMEM>>>();
    // 4) re-quantize ctx and Wproj (reusing x/w digit buffers)
    quant_kernel<<<MTOT, 128>>>(ctx, xq1, xq2, sax);
    quant_kernel<<<DM, 128>>>(Wproj, wq1, wq2, sbw);
    // 5) output projection (int8) -> d_out
    gemm_i8<true><<<dim3(DM/64, MTOT/128), 256, IGEMM_DSMEM>>>(
        xq1, xq2, wq1, wq2, sax, sbw, bproj, out);
}

// round 13
// speedup vs baseline: 1.1471x; 1.0039x over previous
#include <cuda_runtime.h>
#include <cuda_bf16.h>
#include <cstdint>

#define NB 4
#define SQ 1024
#define DM 1280
#define NH 16
#define HD 80
#define MTOT (NB*SQ)      // 4096
#define NQKV (3*DM)       // 3840
#define NROWS (NB*NH*SQ)  // 65536
#define QPAD 96           // int8 q/k rows padded 80 -> 96

// ---------------------------------------------------------------------------
// Scratch (__device__ globals; allocation-free rule)
// ---------------------------------------------------------------------------
__device__ float g_q[NROWS*HD];
__device__ float g_k[NROWS*HD];
__device__ float g_ctx[MTOT*DM];

// int8 2-digit operands (xq*/sax reused for ctx; wq*/sbw reused for Wproj)
__device__ int8_t xq1_g[MTOT*DM],  xq2_g[MTOT*DM];
__device__ int8_t wq1_g[NQKV*DM],  wq2_g[NQKV*DM];
__device__ float  sax_g[MTOT];
__device__ float  sbw_g[NQKV];

// int8 2-digit rotated q/k + per-row scales
__device__ int8_t qq1_g[NROWS*QPAD], qq2_g[NROWS*QPAD];
__device__ int8_t kq1_g[NROWS*QPAD], kq2_g[NROWS*QPAD];
__device__ float  sq_g[NROWS], sk_g[NROWS];

// bf16 hi/lo V (PV stays bf16)
__device__ __nv_bfloat16 vh_g[NROWS*HD], vl_g[NROWS*HD];

// ---------------------------------------------------------------------------
// helpers
// ---------------------------------------------------------------------------
__device__ __forceinline__ uint32_t s2u(const void* p) {
    uint32_t a;
    asm("{ .reg .u64 t; cvta.to.shared.u64 t, %1; cvt.u32.u64 %0, t; }"
        : "=r"(a) : "l"(p));
    return a;
}
__device__ __forceinline__ void ldm_x4(uint32_t* r, uint32_t addr) {
    asm volatile("ldmatrix.sync.aligned.m8n8.x4.shared.b16 {%0,%1,%2,%3}, [%4];"
        : "=r"(r[0]), "=r"(r[1]), "=r"(r[2]), "=r"(r[3]) : "r"(addr));
}
__device__ __forceinline__ void ldm_x4_t(uint32_t* r, uint32_t addr) {
    asm volatile("ldmatrix.sync.aligned.m8n8.x4.trans.shared.b16 {%0,%1,%2,%3}, [%4];"
        : "=r"(r[0]), "=r"(r[1]), "=r"(r[2]), "=r"(r[3]) : "r"(addr));
}
__device__ __forceinline__ void mma16816(float* c, const uint32_t* a,
                                         uint32_t b0, uint32_t b1) {
    asm volatile(
        "mma.sync.aligned.m16n8k16.row.col.f32.bf16.bf16.f32 "
        "{%0,%1,%2,%3}, {%4,%5,%6,%7}, {%8,%9}, {%0,%1,%2,%3};"
        : "+f"(c[0]), "+f"(c[1]), "+f"(c[2]), "+f"(c[3])
        : "r"(a[0]), "r"(a[1]), "r"(a[2]), "r"(a[3]), "r"(b0), "r"(b1));
}
__device__ __forceinline__ void mma_s8(int* c, const uint32_t* a,
                                       uint32_t b0, uint32_t b1) {
    asm volatile(
        "mma.sync.aligned.m16n8k32.row.col.s32.s8.s8.s32 "
        "{%0,%1,%2,%3}, {%4,%5,%6,%7}, {%8,%9}, {%0,%1,%2,%3};"
        : "+r"(c[0]), "+r"(c[1]), "+r"(c[2]), "+r"(c[3])
        : "r"(a[0]), "r"(a[1]), "r"(a[2]), "r"(a[3]), "r"(b0), "r"(b1));
}
__device__ __forceinline__ uint32_t packbf(float a, float b) {
    __nv_bfloat162 t = __floats2bfloat162_rn(a, b);
    return *reinterpret_cast<uint32_t*>(&t);
}
__device__ __forceinline__ void cpasync16(uint32_t dst, const void* src) {
    asm volatile("cp.async.ca.shared.global [%0], [%1], 16;"
        :: "r"(dst), "l"(src) : "memory");
}
#define CP_COMMIT() asm volatile("cp.async.commit_group;" ::: "memory")
#define CP_WAIT0()  asm volatile("cp.async.wait_group 0;" ::: "memory")
#define CP_WAIT1()  asm volatile("cp.async.wait_group 1;" ::: "memory")

// ---------------------------------------------------------------------------
// fp32 -> int8 2-digit row quantization: v = s*(d1 + d2/250), s = rowmax/120.
// ---------------------------------------------------------------------------
__global__ void __launch_bounds__(128) quant_kernel(
    const float* __restrict__ src, int8_t* __restrict__ d1,
    int8_t* __restrict__ d2, float* __restrict__ scale)
{
    const int row = blockIdx.x;
    const int tid = threadIdx.x;
    const float* p = src + (size_t)row * DM;
    float mx = 0.f;
    for (int i = tid; i < DM; i += 128) mx = fmaxf(mx, fabsf(p[i]));
    #pragma unroll
    for (int off = 16; off >= 1; off >>= 1)
        mx = fmaxf(mx, __shfl_xor_sync(0xffffffffu, mx, off));
    __shared__ float smx[4];
    if ((tid & 31) == 0) smx[tid >> 5] = mx;
    __syncthreads();
    mx = fmaxf(fmaxf(smx[0], smx[1]), fmaxf(smx[2], smx[3]));
    const float s = (mx > 0.f) ? mx * (1.f / 120.f) : 1.f;
    const float inv = 1.f / s;
    for (int i = tid; i < DM; i += 128) {
        const float f  = p[i] * inv;
        const float q1 = rintf(f);
        const float q2 = rintf(250.f * (f - q1));
        d1[(size_t)row * DM + i] = (int8_t)(int)q1;
        d2[(size_t)row * DM + i] = (int8_t)(int)q2;
    }
    if (tid == 0) scale[row] = s;
}

// ===========================================================================
// int8 2-digit GEMM: C = sa[m]*sb[n]*(P + X/250) + bias[n].
// CTA 128(M)x128(N), 512 thr, 16 warps as 4(M)x4(N) of 32x32 warp tiles.
// Per-warp code identical to the validated R9 kernel (124 regs).
// K-stage 128 int8, 2-stage cp.async pipeline, 144KB smem, 1 CTA/SM.
// PROJ=false: QKV (scatter q,k fp32 + v bf16 hi/lo). PROJ=true: dense out.
// ===========================================================================
#define IK 128
#define IPITCH 144
#define IMAT (128*IPITCH)              // 18432
#define ISTAGE (4*IMAT)                // 73728
#define IGEMM_DSMEM (2*ISTAGE)         // 147456

template<bool PROJ>
__global__ void __launch_bounds__(512, 1) gemm_i8(
    const int8_t* __restrict__ A1, const int8_t* __restrict__ A2,
    const int8_t* __restrict__ B1, const int8_t* __restrict__ B2,
    const float* __restrict__ sa_v, const float* __restrict__ sb_v,
    const float* __restrict__ bias, float* __restrict__ Cout)
{
    extern __shared__ char dsm_raw[];
    const uint32_t base = s2u(dsm_raw);

    const int tid  = threadIdx.x;
    const int wid  = tid >> 5, lane = tid & 31;
    const int bx = blockIdx.x, by = blockIdx.y;
    const int wm = wid >> 2, wn = wid & 3;    // 4x4 warps, tile 32(M) x 32(N)

    const int8_t* a1p = A1 + (size_t)(by * 128) * DM;
    const int8_t* a2p = A2 + (size_t)(by * 128) * DM;
    const int8_t* b1p = B1 + (size_t)(bx * 128) * DM;
    const int8_t* b2p = B2 + (size_t)(bx * 128) * DM;

    auto ISSUE = [&](int it) {
        const uint32_t sb = base + (it & 1) * ISTAGE;
        const int kof = it * IK;
        const int8_t* mats[4] = { a1p, a2p, b1p, b2p };
        #pragma unroll
        for (int j = 0; j < 8; j++) {
            const int idx = tid + 512 * j;        // 0..4095
            const int mat = idx >> 10;
            const int rem = idx & 1023;
            const int r = rem >> 3, c = rem & 7;
            cpasync16(sb + mat * IMAT + r * IPITCH + c * 16,
                      mats[mat] + (size_t)r * DM + kof + c * 16);
        }
        CP_COMMIT();
    };

    int accP[2][4][4], accX[2][4][4];
    #pragma unroll
    for (int i = 0; i < 2; i++)
        #pragma unroll
        for (int j = 0; j < 4; j++)
            #pragma unroll
            for (int q = 0; q < 4; q++) { accP[i][j][q] = 0; accX[i][j][q] = 0; }

    ISSUE(0); ISSUE(1);

    const int NITI = DM / IK;
    for (int it = 0; it < NITI; ++it) {
        if (it == NITI - 1) { CP_WAIT0(); } else { CP_WAIT1(); }
        __syncthreads();

        const uint32_t sb = base + (it & 1) * ISTAGE;
        #pragma unroll
        for (int kc = 0; kc < 4; kc++) {
            uint32_t Ad1[2][4], Ad2[2][4];
            #pragma unroll
            for (int mf = 0; mf < 2; mf++) {
                const uint32_t aoff =
                    (uint32_t)((wm*32 + mf*16 + (lane & 15)) * IPITCH
                               + kc*32 + (lane >> 4) * 16);
                ldm_x4(Ad1[mf], sb + aoff);
                ldm_x4(Ad2[mf], sb + IMAT + aoff);
            }
            uint32_t Bd1[2][4], Bd2[2][4];
            #pragma unroll
            for (int g = 0; g < 2; g++) {
                const int quad = lane >> 3;
                const uint32_t boff =
                    (uint32_t)((wn*32 + g*16 + (quad >> 1) * 8 + (lane & 7)) * IPITCH
                               + kc*32 + (quad & 1) * 16);
                ldm_x4(Bd1[g], sb + 2*IMAT + boff);
                ldm_x4(Bd2[g], sb + 3*IMAT + boff);
            }
            #pragma unroll
            for (int mf = 0; mf < 2; mf++)
                #pragma unroll
                for (int nb = 0; nb < 4; nb++)
                    mma_s8(accP[mf][nb], Ad1[mf], Bd1[nb>>1][(nb&1)*2], Bd1[nb>>1][(nb&1)*2+1]);
            #pragma unroll
            for (int mf = 0; mf < 2; mf++)
                #pragma unroll
                for (int nb = 0; nb < 4; nb++)
                    mma_s8(accX[mf][nb], Ad1[mf], Bd2[nb>>1][(nb&1)*2], Bd2[nb>>1][(nb&1)*2+1]);
            #pragma unroll
            for (int mf = 0; mf < 2; mf++)
                #pragma unroll
                for (int nb = 0; nb < 4; nb++)
                    mma_s8(accX[mf][nb], Ad2[mf], Bd1[nb>>1][(nb&1)*2], Bd1[nb>>1][(nb&1)*2+1]);
        }
        __syncthreads();
        if (it + 2 < NITI) ISSUE(it + 2);
    }

    #pragma unroll
    for (int mf = 0; mf < 2; mf++)
        #pragma unroll
        for (int nb = 0; nb < 4; nb++)
            #pragma unroll
            for (int ci = 0; ci < 2; ci++) {
                const int m = by*128 + wm*32 + mf*16 + (lane >> 2) + ci*8;
                const int n = bx*128 + wn*32 + nb*8 + (lane & 3) * 2;
                const float sa = sa_v[m];
                float2 v;
                v.x = sa * sb_v[n]   * ((float)accP[mf][nb][2*ci+0]
                        + (float)accX[mf][nb][2*ci+0] * 0.004f) + bias[n];
                v.y = sa * sb_v[n+1] * ((float)accP[mf][nb][2*ci+1]
                        + (float)accX[mf][nb][2*ci+1] * 0.004f) + bias[n+1];
                if (PROJ) {
                    *(float2*)&Cout[(size_t)m * DM + n] = v;
                } else {
                    const int sel = n / DM;
                    const int r2  = n - sel * DM;
                    const int h   = r2 / HD;
                    const int dd  = r2 - h * HD;
                    const int bb  = m >> 10;
                    const int ss  = m & (SQ - 1);
                    const size_t di = (((size_t)bb * NH + h) * SQ + ss) * HD + dd;
                    if (sel == 0)      *(float2*)&g_q[di] = v;
                    else if (sel == 1) *(float2*)&g_k[di] = v;
                    else {
                        __nv_bfloat16 h0 = __float2bfloat16_rn(v.x);
                        __nv_bfloat16 h1 = __float2bfloat16_rn(v.y);
                        *(__nv_bfloat162*)&vh_g[di] = __nv_bfloat162(h0, h1);
                        *(__nv_bfloat162*)&vl_g[di] = __floats2bfloat162_rn(
                            v.x - __bfloat162float(h0), v.y - __bfloat162float(h1));
                    }
                }
            }
}

// ---------------------------------------------------------------------------
// RoPE + int8 2-digit quantization. One warp per (b,h,s) row of 80.
// ---------------------------------------------------------------------------
__global__ void __launch_bounds__(256) rope_quant(
    const float* __restrict__ cosp, const float* __restrict__ sinp)
{
    const int row  = (blockIdx.x << 3) + (threadIdx.x >> 5);   // < NROWS
    const int lane = threadIdx.x & 31;
    const int ss   = row & (SQ - 1);
    const size_t base = (size_t)row * HD;

    const int d0 = lane;                 // 0..31 (< 40)
    const bool two = lane < 8;           // second pair d = lane+32 (< 40)

    const float c1 = cosp[ss*HD + d0],      s1 = sinp[ss*HD + d0];
    const float c2 = cosp[ss*HD + d0 + 40], s2 = sinp[ss*HD + d0 + 40];
    float a, b2;

    a = g_q[base + d0]; b2 = g_q[base + d0 + 40];
    float qo1 = a*c1 - b2*s1, qo2 = b2*c2 + a*s2;
    a = g_k[base + d0]; b2 = g_k[base + d0 + 40];
    float ko1 = a*c1 - b2*s1, ko2 = b2*c2 + a*s2;

    float qo3 = 0.f, qo4 = 0.f, ko3 = 0.f, ko4 = 0.f;
    if (two) {
        const int d = lane + 32;
        const float cc1 = cosp[ss*HD + d],      ss1 = sinp[ss*HD + d];
        const float cc2 = cosp[ss*HD + d + 40], ss2 = sinp[ss*HD + d + 40];
        a = g_q[base + d]; b2 = g_q[base + d + 40];
        qo3 = a*cc1 - b2*ss1; qo4 = b2*cc2 + a*ss2;
        a = g_k[base + d]; b2 = g_k[base + d + 40];
        ko3 = a*cc1 - b2*ss1; ko4 = b2*cc2 + a*ss2;
    }

    float qm = fmaxf(fmaxf(fabsf(qo1), fabsf(qo2)), fmaxf(fabsf(qo3), fabsf(qo4)));
    float km = fmaxf(fmaxf(fabsf(ko1), fabsf(ko2)), fmaxf(fabsf(ko3), fabsf(ko4)));
    #pragma unroll
    for (int off = 16; off >= 1; off >>= 1) {
        qm = fmaxf(qm, __shfl_xor_sync(0xffffffffu, qm, off));
        km = fmaxf(km, __shfl_xor_sync(0xffffffffu, km, off));
    }
    const float sq = (qm > 0.f) ? qm * (1.f/120.f) : 1.f;
    const float sk = (km > 0.f) ? km * (1.f/120.f) : 1.f;
    const float iq = 1.f / sq, ik = 1.f / sk;

    const size_t rb = (size_t)row * QPAD;
    auto putq = [&](int d, float v) {
        const float f = v * iq;
        const float q1 = rintf(f);
        qq1_g[rb + d] = (int8_t)(int)q1;
        qq2_g[rb + d] = (int8_t)(int)rintf(250.f * (f - q1));
    };
    auto putk = [&](int d, float v) {
        const float f = v * ik;
        const float q1 = rintf(f);
        kq1_g[rb + d] = (int8_t)(int)q1;
        kq2_g[rb + d] = (int8_t)(int)rintf(250.f * (f - q1));
    };
    putq(d0, qo1); putq(d0 + 40, qo2);
    putk(d0, ko1); putk(d0 + 40, ko2);
    if (two) {
        putq(d0 + 32, qo3); putq(d0 + 72, qo4);
        putk(d0 + 32, ko3); putk(d0 + 72, ko4);
    }
    if (lane < 16) {  // zero pad cols 80..95
        qq1_g[rb + 80 + lane] = 0; qq2_g[rb + 80 + lane] = 0;
        kq1_g[rb + 80 + lane] = 0; kq2_g[rb + 80 + lane] = 0;
    }
    if (lane == 0) { sq_g[row] = sq; sk_g[row] = sk; }
}

// ===========================================================================
// Flash attention: S-phase int8 2-digit (k32), PV bf16 3-pass. (R10 exact.)
// CTA = (q-tile 128 rows, bh), 8 warps. Double-buffered K/V. fp32 ctx out.
// ===========================================================================
#define QIP 112                          // int8 row pitch in smem (96 + 16)
#define AQ1 0                            // QI1: 128*112 = 14336
#define AQ2 14336
#define AKVQ 28672
#define SK1o 0
#define SK2o 7168
#define SVHo 14336
#define SVLo 25600
#define SSKo 36864                       // 64 floats
#define KVSTG 37120
#define ATTN_SMEM (AKVQ + 2*KVSTG)       // 102912
#define APITCH 176                       // bf16 V row pitch

__global__ void __launch_bounds__(256) attn_tc()
{
    extern __shared__ char dsm_raw[];
    const uint32_t base = s2u(dsm_raw);

    const int tid = threadIdx.x;
    const int w = tid >> 5, lane = tid & 31;
    const int qt = blockIdx.x, bh = blockIdx.y;
    const int b = bh >> 4, h = bh & 15;
    const float scale = 0.11180339887498948f;  // 1/sqrt(80)

    const size_t row0 = (size_t)bh * SQ;
    const size_t qrow0 = row0 + qt * 128;

    auto ISSUE_KV = [&](int kt) {
        const uint32_t sb = base + AKVQ + (kt & 1) * KVSTG;
        const size_t kr = row0 + kt * 64;
        #pragma unroll
        for (int j = 0; j < 9; j++) {
            const int idx = tid + 256 * j;        // 0..2063 used
            if (idx < 384) {
                const int r = idx / 6, c = idx - r * 6;
                cpasync16(sb + SK1o + r * QIP + c * 16,
                          kq1_g + (kr + r) * QPAD + c * 16);
            } else if (idx < 768) {
                const int l = idx - 384, r = l / 6, c = l - r * 6;
                cpasync16(sb + SK2o + r * QIP + c * 16,
                          kq2_g + (kr + r) * QPAD + c * 16);
            } else if (idx < 1408) {
                const int l = idx - 768, r = l / 10, c = l - r * 10;
                cpasync16(sb + SVHo + r * APITCH + c * 16,
                          vh_g + (kr + r) * HD + c * 8);
            } else if (idx < 2048) {
                const int l = idx - 1408, r = l / 10, c = l - r * 10;
                cpasync16(sb + SVLo + r * APITCH + c * 16,
                          vl_g + (kr + r) * HD + c * 8);
            } else if (idx < 2064) {
                const int l = idx - 2048;
                cpasync16(sb + SSKo + l * 16, sk_g + kr + l * 4);
            }
        }
        CP_COMMIT();
    };

    // Q int8 tiles (once): 128 rows x 6 chunks x 2 mats = 1536
    {
        #pragma unroll
        for (int j = 0; j < 6; j++) {
            const int idx = tid + 256 * j;
            const int mat = idx / 768;
            const int rem = idx - mat * 768;
            const int r = rem / 6, c = rem - r * 6;
            cpasync16(base + (mat ? AQ2 : AQ1) + r * QIP + c * 16,
                      (mat ? qq2_g : qq1_g) + (qrow0 + r) * QPAD + c * 16);
        }
        CP_COMMIT();
    }
    ISSUE_KV(0);

    const float sq0 = sq_g[qrow0 + w*16 + (lane >> 2)];
    const float sq1 = sq_g[qrow0 + w*16 + (lane >> 2) + 8];

    float oacc[10][4];
    #pragma unroll
    for (int i = 0; i < 10; i++)
        #pragma unroll
        for (int j = 0; j < 4; j++) oacc[i][j] = 0.f;
    float m0 = -1e30f, m1 = -1e30f, l0 = 0.f, l1 = 0.f;

    for (int kt = 0; kt < 16; kt++) {
        if (kt + 1 < 16) { ISSUE_KV(kt + 1); CP_WAIT1(); } else { CP_WAIT0(); }
        __syncthreads();

        const uint32_t kvb = base + AKVQ + (kt & 1) * KVSTG;
        const float* skf = (const float*)(dsm_raw + AKVQ + (kt & 1) * KVSTG + SSKo);

        // ---- S = Q K^T, int8 2-digit (3 k-chunks x 3 passes) ----
        int accP[8][4], accX[8][4];
        #pragma unroll
        for (int i = 0; i < 8; i++)
            #pragma unroll
            for (int j = 0; j < 4; j++) { accP[i][j] = 0; accX[i][j] = 0; }

        #pragma unroll
        for (int kc = 0; kc < 3; kc++) {
            uint32_t Ad1[4], Ad2[4];
            const uint32_t aoff =
                (uint32_t)((w*16 + (lane & 15)) * QIP + kc*32 + (lane >> 4) * 16);
            ldm_x4(Ad1, base + AQ1 + aoff);
            ldm_x4(Ad2, base + AQ2 + aoff);
            uint32_t Bd1[4][4], Bd2[4][4];
            #pragma unroll
            for (int g = 0; g < 4; g++) {
                const int quad = lane >> 3;
                const uint32_t boff =
                    (uint32_t)((g*16 + (quad >> 1) * 8 + (lane & 7)) * QIP
                               + kc*32 + (quad & 1) * 16);
                ldm_x4(Bd1[g], kvb + SK1o + boff);
                ldm_x4(Bd2[g], kvb + SK2o + boff);
            }
            #pragma unroll
            for (int nb = 0; nb < 8; nb++)
                mma_s8(accP[nb], Ad1, Bd1[nb>>1][(nb&1)*2], Bd1[nb>>1][(nb&1)*2+1]);
            #pragma unroll
            for (int nb = 0; nb < 8; nb++)
                mma_s8(accX[nb], Ad1, Bd2[nb>>1][(nb&1)*2], Bd2[nb>>1][(nb&1)*2+1]);
            #pragma unroll
            for (int nb = 0; nb < 8; nb++)
                mma_s8(accX[nb], Ad2, Bd1[nb>>1][(nb&1)*2], Bd1[nb>>1][(nb&1)*2+1]);
        }

        // ---- reconstruct scores + online softmax ----
        float sacc[8][4];
        #pragma unroll
        for (int nb = 0; nb < 8; nb++) {
            const int col = nb*8 + (lane & 3) * 2;
            const float k0 = skf[col] * scale, k1 = skf[col + 1] * scale;
            sacc[nb][0] = sq0 * k0 * ((float)accP[nb][0] + (float)accX[nb][0] * 0.004f);
            sacc[nb][1] = sq0 * k1 * ((float)accP[nb][1] + (float)accX[nb][1] * 0.004f);
            sacc[nb][2] = sq1 * k0 * ((float)accP[nb][2] + (float)accX[nb][2] * 0.004f);
            sacc[nb][3] = sq1 * k1 * ((float)accP[nb][3] + (float)accX[nb][3] * 0.004f);
        }

        float mx0 = -1e30f, mx1 = -1e30f;
        #pragma unroll
        for (int nb = 0; nb < 8; nb++) {
            mx0 = fmaxf(mx0, fmaxf(sacc[nb][0], sacc[nb][1]));
            mx1 = fmaxf(mx1, fmaxf(sacc[nb][2], sacc[nb][3]));
        }
        mx0 = fmaxf(mx0, __shfl_xor_sync(0xffffffffu, mx0, 1));
        mx0 = fmaxf(mx0, __shfl_xor_sync(0xffffffffu, mx0, 2));
        mx1 = fmaxf(mx1, __shfl_xor_sync(0xffffffffu, mx1, 1));
        mx1 = fmaxf(mx1, __shfl_xor_sync(0xffffffffu, mx1, 2));

        const float mn0 = fmaxf(m0, mx0), mn1 = fmaxf(m1, mx1);
        const float al0 = __expf(m0 - mn0), al1 = __expf(m1 - mn1);
        m0 = mn0; m1 = mn1;

        float rs0 = 0.f, rs1 = 0.f;
        #pragma unroll
        for (int nb = 0; nb < 8; nb++) {
            sacc[nb][0] = __expf(sacc[nb][0] - m0);
            sacc[nb][1] = __expf(sacc[nb][1] - m0);
            sacc[nb][2] = __expf(sacc[nb][2] - m1);
            sacc[nb][3] = __expf(sacc[nb][3] - m1);
            rs0 += sacc[nb][0] + sacc[nb][1];
            rs1 += sacc[nb][2] + sacc[nb][3];
        }
        rs0 += __shfl_xor_sync(0xffffffffu, rs0, 1);
        rs0 += __shfl_xor_sync(0xffffffffu, rs0, 2);
        rs1 += __shfl_xor_sync(0xffffffffu, rs1, 1);
        rs1 += __shfl_xor_sync(0xffffffffu, rs1, 2);
        l0 = l0 * al0 + rs0;
        l1 = l1 * al1 + rs1;

        #pragma unroll
        for (int nb = 0; nb < 10; nb++) {
            oacc[nb][0] *= al0; oacc[nb][1] *= al0;
            oacc[nb][2] *= al1; oacc[nb][3] *= al1;
        }

        // ---- O += P @ V, bf16 3-pass ----
        #pragma unroll
        for (int kc = 0; kc < 4; kc++) {
            uint32_t Pa_h[4], Pa_l[4];
            #pragma unroll
            for (int half2i = 0; half2i < 2; half2i++) {
                const int nb = 2*kc + half2i;
                float f0 = sacc[nb][0], f1 = sacc[nb][1];
                float f2 = sacc[nb][2], f3 = sacc[nb][3];
                float h0 = __bfloat162float(__float2bfloat16_rn(f0));
                float h1 = __bfloat162float(__float2bfloat16_rn(f1));
                float h2 = __bfloat162float(__float2bfloat16_rn(f2));
                float h3 = __bfloat162float(__float2bfloat16_rn(f3));
                Pa_h[2*half2i+0] = packbf(h0, h1);
                Pa_h[2*half2i+1] = packbf(h2, h3);
                Pa_l[2*half2i+0] = packbf(f0 - h0, f1 - h1);
                Pa_l[2*half2i+1] = packbf(f2 - h2, f3 - h3);
            }
            uint32_t Vh4[5][4], Vl4[5][4];
            #pragma unroll
            for (int vg = 0; vg < 5; vg++) {
                const int vrow = kc*16 + ((lane >> 3) & 1) * 8 + (lane & 7);
                const int vcol = vg*16 + (lane >> 4) * 8;
                const uint32_t voff = (uint32_t)(vrow * APITCH + vcol * 2);
                ldm_x4_t(Vh4[vg], kvb + SVHo + voff);
                ldm_x4_t(Vl4[vg], kvb + SVLo + voff);
            }
            #pragma unroll
            for (int vg = 0; vg < 5; vg++)
                #pragma unroll
                for (int hh = 0; hh < 2; hh++)
                    mma16816(oacc[vg*2+hh], Pa_h, Vh4[vg][2*hh], Vh4[vg][2*hh+1]);
            #pragma unroll
            for (int vg = 0; vg < 5; vg++)
                #pragma unroll
                for (int hh = 0; hh < 2; hh++)
                    mma16816(oacc[vg*2+hh], Pa_l, Vh4[vg][2*hh], Vh4[vg][2*hh+1]);
            #pragma unroll
            for (int vg = 0; vg < 5; vg++)
                #pragma unroll
                for (int hh = 0; hh < 2; hh++)
                    mma16816(oacc[vg*2+hh], Pa_h, Vl4[vg][2*hh], Vl4[vg][2*hh+1]);
        }
        __syncthreads();
    }

    // ---- finalize: normalize, write fp32 ctx ----
    const float inv0 = 1.f / l0, inv1 = 1.f / l1;
    const int s0 = qt*128 + w*16 + (lane >> 2);
    const int s1 = s0 + 8;
    #pragma unroll
    for (int nb = 0; nb < 10; nb++) {
        const int d = nb*8 + (lane & 3) * 2;
        {
            float2 v; v.x = oacc[nb][0] * inv0; v.y = oacc[nb][1] * inv0;
            *(float2*)&g_ctx[((size_t)b * SQ + s0) * DM + h * HD + d] = v;
        }
        {
            float2 v; v.x = oacc[nb][2] * inv1; v.y = oacc[nb][3] * inv1;
            *(float2*)&g_ctx[((size_t)b * SQ + s1) * DM + h * HD + d] = v;
        }
    }
}

// ---------------------------------------------------------------------------
extern "C" void kernel_launch(void* const* d_in, const int* in_sizes, int n_in,
                              void* d_out, int out_size)
{
    (void)in_sizes; (void)n_in; (void)out_size;
    const float* x     = (const float*)d_in[0];
    const float* cosp  = (const float*)d_in[1];
    const float* sinp  = (const float*)d_in[2];
    const float* Wqkv  = (const float*)d_in[3];
    const float* bqkv  = (const float*)d_in[4];
    const float* Wproj = (const float*)d_in[5];
    const float* bproj = (const float*)d_in[6];
    float* out = (float*)d_out;

    cudaFuncSetAttribute(gemm_i8<false>,
                         cudaFuncAttributeMaxDynamicSharedMemorySize, IGEMM_DSMEM);
    cudaFuncSetAttribute(gemm_i8<true>,
                         cudaFuncAttributeMaxDynamicSharedMemorySize, IGEMM_DSMEM);
    cudaFuncSetAttribute(attn_tc,
                         cudaFuncAttributeMaxDynamicSharedMemorySize, ATTN_SMEM);

    int8_t *xq1, *xq2, *wq1, *wq2;
    float *sax, *sbw, *ctx;
    cudaGetSymbolAddress((void**)&xq1, xq1_g);
    cudaGetSymbolAddress((void**)&xq2, xq2_g);
    cudaGetSymbolAddress((void**)&wq1, wq1_g);
    cudaGetSymbolAddress((void**)&wq2, wq2_g);
    cudaGetSymbolAddress((void**)&sax, sax_g);
    cudaGetSymbolAddress((void**)&sbw, sbw_g);
    cudaGetSymbolAddress((void**)&ctx, g_ctx);

    // 0) quantize x, Wqkv
    quant_kernel<<<MTOT, 128>>>(x, xq1, xq2, sax);
    quant_kernel<<<NQKV, 128>>>(Wqkv, wq1, wq2, sbw);
    // 1) QKV GEMM (int8, 128x128 tiles): q,k fp32 head-major + v bf16 hi/lo
    gemm_i8<false><<<dim3(NQKV/128, MTOT/128), 512, IGEMM_DSMEM>>>(
        xq1, xq2, wq1, wq2, sax, sbw, bqkv, nullptr);
    // 2) RoPE + int8 quant -> qq/kq + scales
    rope_quant<<<NROWS/8, 256>>>(cosp, sinp);
    // 3) attention (int8 S, bf16 PV) -> fp32 ctx
    attn_tc<<<dim3(SQ/128, NB*NH), 256, ATTN_SMEM>>>();
    // 4) re-quantize ctx and Wproj (reusing x/w digit buffers)
    quant_kernel<<<MTOT, 128>>>(ctx, xq1, xq2, sax);
    quant_kernel<<<DM, 128>>>(Wproj, wq1, wq2, sbw);
    // 5) output projection (int8, 128x128 tiles) -> d_out
    gemm_i8<true><<<dim3(DM/128, MTOT/128), 512, IGEMM_DSMEM>>>(
        xq1, xq2, wq1, wq2, sax, sbw, bproj, out);
}

// round 14
// speedup vs baseline: 1.1789x; 1.0278x over previous
#include <cuda_runtime.h>
#include <cuda_bf16.h>
#include <cstdint>

#define NB 4
#define SQ 1024
#define DM 1280
#define NH 16
#define HD 80
#define MTOT (NB*SQ)      // 4096
#define NQKV (3*DM)       // 3840
#define NROWS (NB*NH*SQ)  // 65536
#define QPAD 96           // int8 q/k rows padded 80 -> 96

// ---------------------------------------------------------------------------
// Scratch (__device__ globals; allocation-free rule)
// ---------------------------------------------------------------------------
__device__ float g_q[NROWS*HD];
__device__ float g_k[NROWS*HD];
__device__ float g_ctx[MTOT*DM];

// int8 2-digit operands (xq*/sax reused for ctx; wq*/sbw reused for Wproj)
__device__ int8_t xq1_g[MTOT*DM],  xq2_g[MTOT*DM];
__device__ int8_t wq1_g[NQKV*DM],  wq2_g[NQKV*DM];
__device__ float  sax_g[MTOT];
__device__ float  sbw_g[NQKV];

// int8 2-digit rotated q/k + per-row scales
__device__ int8_t qq1_g[NROWS*QPAD], qq2_g[NROWS*QPAD];
__device__ int8_t kq1_g[NROWS*QPAD], kq2_g[NROWS*QPAD];
__device__ float  sq_g[NROWS], sk_g[NROWS];

// bf16 hi/lo V (PV stays bf16)
__device__ __nv_bfloat16 vh_g[NROWS*HD], vl_g[NROWS*HD];

// ---------------------------------------------------------------------------
// helpers
// ---------------------------------------------------------------------------
__device__ __forceinline__ uint32_t s2u(const void* p) {
    uint32_t a;
    asm("{ .reg .u64 t; cvta.to.shared.u64 t, %1; cvt.u32.u64 %0, t; }"
        : "=r"(a) : "l"(p));
    return a;
}
__device__ __forceinline__ void ldm_x4(uint32_t* r, uint32_t addr) {
    asm volatile("ldmatrix.sync.aligned.m8n8.x4.shared.b16 {%0,%1,%2,%3}, [%4];"
        : "=r"(r[0]), "=r"(r[1]), "=r"(r[2]), "=r"(r[3]) : "r"(addr));
}
__device__ __forceinline__ void ldm_x4_t(uint32_t* r, uint32_t addr) {
    asm volatile("ldmatrix.sync.aligned.m8n8.x4.trans.shared.b16 {%0,%1,%2,%3}, [%4];"
        : "=r"(r[0]), "=r"(r[1]), "=r"(r[2]), "=r"(r[3]) : "r"(addr));
}
__device__ __forceinline__ void mma16816(float* c, const uint32_t* a,
                                         uint32_t b0, uint32_t b1) {
    asm volatile(
        "mma.sync.aligned.m16n8k16.row.col.f32.bf16.bf16.f32 "
        "{%0,%1,%2,%3}, {%4,%5,%6,%7}, {%8,%9}, {%0,%1,%2,%3};"
        : "+f"(c[0]), "+f"(c[1]), "+f"(c[2]), "+f"(c[3])
        : "r"(a[0]), "r"(a[1]), "r"(a[2]), "r"(a[3]), "r"(b0), "r"(b1));
}
__device__ __forceinline__ void mma_s8(int* c, const uint32_t* a,
                                       uint32_t b0, uint32_t b1) {
    asm volatile(
        "mma.sync.aligned.m16n8k32.row.col.s32.s8.s8.s32 "
        "{%0,%1,%2,%3}, {%4,%5,%6,%7}, {%8,%9}, {%0,%1,%2,%3};"
        : "+r"(c[0]), "+r"(c[1]), "+r"(c[2]), "+r"(c[3])
        : "r"(a[0]), "r"(a[1]), "r"(a[2]), "r"(a[3]), "r"(b0), "r"(b1));
}
__device__ __forceinline__ uint32_t packbf(float a, float b) {
    __nv_bfloat162 t = __floats2bfloat162_rn(a, b);
    return *reinterpret_cast<uint32_t*>(&t);
}
__device__ __forceinline__ void cpasync16(uint32_t dst, const void* src) {
    asm volatile("cp.async.ca.shared.global [%0], [%1], 16;"
        :: "r"(dst), "l"(src) : "memory");
}
#define CP_COMMIT() asm volatile("cp.async.commit_group;" ::: "memory")
#define CP_WAIT0()  asm volatile("cp.async.wait_group 0;" ::: "memory")
#define CP_WAIT1()  asm volatile("cp.async.wait_group 1;" ::: "memory")

// ---------------------------------------------------------------------------
// Fused fp32 -> int8 2-digit row quantization for TWO tensors (same DM cols).
// v = s*(d1 + d2/250), s = rowmax/120. One 128-thr block per row.
// ---------------------------------------------------------------------------
__global__ void __launch_bounds__(128) quant2_kernel(
    const float* __restrict__ s0, int8_t* __restrict__ a1,
    int8_t* __restrict__ a2, float* __restrict__ sc0, int n0,
    const float* __restrict__ s1, int8_t* __restrict__ b1,
    int8_t* __restrict__ b2, float* __restrict__ sc1)
{
    const int bid = blockIdx.x;
    const float* src; int8_t* d1; int8_t* d2; float* scale; int row;
    if (bid < n0) { src = s0; d1 = a1; d2 = a2; scale = sc0; row = bid; }
    else          { src = s1; d1 = b1; d2 = b2; scale = sc1; row = bid - n0; }

    const int tid = threadIdx.x;
    const float* p = src + (size_t)row * DM;
    float mx = 0.f;
    for (int i = tid; i < DM; i += 128) mx = fmaxf(mx, fabsf(p[i]));
    #pragma unroll
    for (int off = 16; off >= 1; off >>= 1)
        mx = fmaxf(mx, __shfl_xor_sync(0xffffffffu, mx, off));
    __shared__ float smx[4];
    if ((tid & 31) == 0) smx[tid >> 5] = mx;
    __syncthreads();
    mx = fmaxf(fmaxf(smx[0], smx[1]), fmaxf(smx[2], smx[3]));
    const float s = (mx > 0.f) ? mx * (1.f / 120.f) : 1.f;
    const float inv = 1.f / s;
    for (int i = tid; i < DM; i += 128) {
        const float f  = p[i] * inv;
        const float q1 = rintf(f);
        const float q2 = rintf(250.f * (f - q1));
        d1[(size_t)row * DM + i] = (int8_t)(int)q1;
        d2[(size_t)row * DM + i] = (int8_t)(int)q2;
    }
    if (tid == 0) scale[row] = s;
}

// ===========================================================================
// int8 2-digit GEMM core (R10 exact): C = sa[m]*sb[n]*(P + X/250) + bias[n].
// CTA 128(M)x64(N), 256 thr, 8 warps of 32x32, K-stage 128 int8, 2-stage.
// PROJ=false: QKV (scatter q,k fp32 + v bf16 hi/lo). PROJ=true: dense out.
// ===========================================================================
#define IK 128
#define IPITCH 144
#define IOFF_A2 (128*IPITCH)
#define IOFF_B1 (2*128*IPITCH)
#define IOFF_B2 (IOFF_B1 + 64*IPITCH)
#define ISTAGE (IOFF_B2 + 64*IPITCH)
#define IGEMM_DSMEM (2*ISTAGE)         // 110592

template<bool PROJ>
__global__ void __launch_bounds__(256, 2) gemm_i8(
    const int8_t* __restrict__ A1, const int8_t* __restrict__ A2,
    const int8_t* __restrict__ B1, const int8_t* __restrict__ B2,
    const float* __restrict__ sa_v, const float* __restrict__ sb_v,
    const float* __restrict__ bias, float* __restrict__ Cout)
{
    extern __shared__ char dsm_raw[];
    const uint32_t base = s2u(dsm_raw);

    const int tid  = threadIdx.x;
    const int wid  = tid >> 5, lane = tid & 31;
    const int bx = blockIdx.x, by = blockIdx.y;
    const int wm = wid >> 1, wn = wid & 1;    // warp tile 32(M) x 32(N)

    const int8_t* a1p = A1 + (size_t)(by * 128) * DM;
    const int8_t* a2p = A2 + (size_t)(by * 128) * DM;
    const int8_t* b1p = B1 + (size_t)(bx * 64) * DM;
    const int8_t* b2p = B2 + (size_t)(bx * 64) * DM;

    auto ISSUE = [&](int it) {
        const uint32_t sb = base + (it & 1) * ISTAGE;
        const int kof = it * IK;
        #pragma unroll
        for (int j = 0; j < 12; j++) {
            const int idx = tid + 256 * j;
            int local; uint32_t moff; const int8_t* srcp;
            if (j < 4)       { local = idx;        moff = 0;       srcp = a1p; }
            else if (j < 8)  { local = idx - 1024; moff = IOFF_A2; srcp = a2p; }
            else if (j < 10) { local = idx - 2048; moff = IOFF_B1; srcp = b1p; }
            else             { local = idx - 2560; moff = IOFF_B2; srcp = b2p; }
            const int r = local >> 3, c = local & 7;
            cpasync16(sb + moff + r * IPITCH + c * 16,
                      srcp + (size_t)r * DM + kof + c * 16);
        }
        CP_COMMIT();
    };

    int accP[2][4][4], accX[2][4][4];
    #pragma unroll
    for (int i = 0; i < 2; i++)
        #pragma unroll
        for (int j = 0; j < 4; j++)
            #pragma unroll
            for (int q = 0; q < 4; q++) { accP[i][j][q] = 0; accX[i][j][q] = 0; }

    ISSUE(0); ISSUE(1);

    const int NITI = DM / IK;
    for (int it = 0; it < NITI; ++it) {
        if (it == NITI - 1) { CP_WAIT0(); } else { CP_WAIT1(); }
        __syncthreads();

        const uint32_t sb = base + (it & 1) * ISTAGE;
        #pragma unroll
        for (int kc = 0; kc < 4; kc++) {
            uint32_t Ad1[2][4], Ad2[2][4];
            #pragma unroll
            for (int mf = 0; mf < 2; mf++) {
                const uint32_t aoff =
                    (uint32_t)((wm*32 + mf*16 + (lane & 15)) * IPITCH
                               + kc*32 + (lane >> 4) * 16);
                ldm_x4(Ad1[mf], sb + aoff);
                ldm_x4(Ad2[mf], sb + IOFF_A2 + aoff);
            }
            uint32_t Bd1[2][4], Bd2[2][4];
            #pragma unroll
            for (int g = 0; g < 2; g++) {
                const int quad = lane >> 3;
                const uint32_t boff =
                    (uint32_t)((wn*32 + g*16 + (quad >> 1) * 8 + (lane & 7)) * IPITCH
                               + kc*32 + (quad & 1) * 16);
                ldm_x4(Bd1[g], sb + IOFF_B1 + boff);
                ldm_x4(Bd2[g], sb + IOFF_B2 + boff);
            }
            #pragma unroll
            for (int mf = 0; mf < 2; mf++)
                #pragma unroll
                for (int nb = 0; nb < 4; nb++)
                    mma_s8(accP[mf][nb], Ad1[mf], Bd1[nb>>1][(nb&1)*2], Bd1[nb>>1][(nb&1)*2+1]);
            #pragma unroll
            for (int mf = 0; mf < 2; mf++)
                #pragma unroll
                for (int nb = 0; nb < 4; nb++)
                    mma_s8(accX[mf][nb], Ad1[mf], Bd2[nb>>1][(nb&1)*2], Bd2[nb>>1][(nb&1)*2+1]);
            #pragma unroll
            for (int mf = 0; mf < 2; mf++)
                #pragma unroll
                for (int nb = 0; nb < 4; nb++)
                    mma_s8(accX[mf][nb], Ad2[mf], Bd1[nb>>1][(nb&1)*2], Bd1[nb>>1][(nb&1)*2+1]);
        }
        __syncthreads();
        if (it + 2 < NITI) ISSUE(it + 2);
    }

    #pragma unroll
    for (int mf = 0; mf < 2; mf++)
        #pragma unroll
        for (int nb = 0; nb < 4; nb++)
            #pragma unroll
            for (int ci = 0; ci < 2; ci++) {
                const int m = by*128 + wm*32 + mf*16 + (lane >> 2) + ci*8;
                const int n = bx*64 + wn*32 + nb*8 + (lane & 3) * 2;
                const float sa = sa_v[m];
                float2 v;
                v.x = sa * sb_v[n]   * ((float)accP[mf][nb][2*ci+0]
                        + (float)accX[mf][nb][2*ci+0] * 0.004f) + bias[n];
                v.y = sa * sb_v[n+1] * ((float)accP[mf][nb][2*ci+1]
                        + (float)accX[mf][nb][2*ci+1] * 0.004f) + bias[n+1];
                if (PROJ) {
                    *(float2*)&Cout[(size_t)m * DM + n] = v;
                } else {
                    const int sel = n / DM;
                    const int r2  = n - sel * DM;
                    const int h   = r2 / HD;
                    const int dd  = r2 - h * HD;
                    const int bb  = m >> 10;
                    const int ss  = m & (SQ - 1);
                    const size_t di = (((size_t)bb * NH + h) * SQ + ss) * HD + dd;
                    if (sel == 0)      *(float2*)&g_q[di] = v;
                    else if (sel == 1) *(float2*)&g_k[di] = v;
                    else {
                        __nv_bfloat16 h0 = __float2bfloat16_rn(v.x);
                        __nv_bfloat16 h1 = __float2bfloat16_rn(v.y);
                        *(__nv_bfloat162*)&vh_g[di] = __nv_bfloat162(h0, h1);
                        *(__nv_bfloat162*)&vl_g[di] = __floats2bfloat162_rn(
                            v.x - __bfloat162float(h0), v.y - __bfloat162float(h1));
                    }
                }
            }
}

// ---------------------------------------------------------------------------
// RoPE + int8 2-digit quantization, vectorized. One warp per (b,h,s) row.
// Lanes 0-9: q, d=4L..4L+3 (+ the paired d+40 block). Lanes 10-19: k.
// Lanes 20-23: zero-pad cols 80..95. float4 loads, u32 packed digit stores.
// ---------------------------------------------------------------------------
__global__ void __launch_bounds__(256) rope_quant(
    const float* __restrict__ cosp, const float* __restrict__ sinp)
{
    const int row  = (blockIdx.x << 3) + (threadIdx.x >> 5);   // < NROWS
    const int lane = threadIdx.x & 31;
    const int ss   = row & (SQ - 1);
    const size_t base = (size_t)row * HD;
    const size_t rb   = (size_t)row * QPAD;

    const bool isQ = lane < 10;
    const bool isK = lane >= 10 && lane < 20;
    const int  i4  = isQ ? lane : (lane - 10);   // 0..9
    const int  d   = i4 * 4;

    float lo[4], hi[4];
    float m = 0.f;
    if (isQ || isK) {
        const float* t = isQ ? g_q : g_k;
        const float4 ta = *(const float4*)&t[base + d];
        const float4 tb = *(const float4*)&t[base + d + 40];
        const float4 ca = *(const float4*)&cosp[ss*HD + d];
        const float4 cb = *(const float4*)&cosp[ss*HD + d + 40];
        const float4 sa = *(const float4*)&sinp[ss*HD + d];
        const float4 sb = *(const float4*)&sinp[ss*HD + d + 40];
        lo[0] = ta.x*ca.x - tb.x*sa.x;  hi[0] = tb.x*cb.x + ta.x*sb.x;
        lo[1] = ta.y*ca.y - tb.y*sa.y;  hi[1] = tb.y*cb.y + ta.y*sb.y;
        lo[2] = ta.z*ca.z - tb.z*sa.z;  hi[2] = tb.z*cb.z + ta.z*sb.z;
        lo[3] = ta.w*ca.w - tb.w*sa.w;  hi[3] = tb.w*cb.w + ta.w*sb.w;
        #pragma unroll
        for (int e = 0; e < 4; e++)
            m = fmaxf(m, fmaxf(fabsf(lo[e]), fabsf(hi[e])));
    }

    float qm = isQ ? m : 0.f;
    float km = isK ? m : 0.f;
    #pragma unroll
    for (int off = 16; off >= 1; off >>= 1) {
        qm = fmaxf(qm, __shfl_xor_sync(0xffffffffu, qm, off));
        km = fmaxf(km, __shfl_xor_sync(0xffffffffu, km, off));
    }
    const float sq = (qm > 0.f) ? qm * (1.f/120.f) : 1.f;
    const float sk = (km > 0.f) ? km * (1.f/120.f) : 1.f;

    if (isQ || isK) {
        const float inv = isQ ? (1.f / sq) : (1.f / sk);
        int8_t* o1 = isQ ? qq1_g : kq1_g;
        int8_t* o2 = isQ ? qq2_g : kq2_g;
        uint32_t w1lo = 0, w2lo = 0, w1hi = 0, w2hi = 0;
        #pragma unroll
        for (int e = 0; e < 4; e++) {
            float f  = lo[e] * inv;
            float q1 = rintf(f);
            int   i1 = (int)q1;
            int   i2 = (int)rintf(250.f * (f - q1));
            w1lo |= (uint32_t)(i1 & 0xFF) << (8 * e);
            w2lo |= (uint32_t)(i2 & 0xFF) << (8 * e);
            f  = hi[e] * inv;
            q1 = rintf(f);
            i1 = (int)q1;
            i2 = (int)rintf(250.f * (f - q1));
            w1hi |= (uint32_t)(i1 & 0xFF) << (8 * e);
            w2hi |= (uint32_t)(i2 & 0xFF) << (8 * e);
        }
        *(uint32_t*)&o1[rb + d]      = w1lo;
        *(uint32_t*)&o2[rb + d]      = w2lo;
        *(uint32_t*)&o1[rb + d + 40] = w1hi;
        *(uint32_t*)&o2[rb + d + 40] = w2hi;
    } else if (lane < 24) {
        const size_t po = rb + 80 + (lane - 20) * 4;
        *(uint32_t*)&qq1_g[po] = 0u; *(uint32_t*)&qq2_g[po] = 0u;
        *(uint32_t*)&kq1_g[po] = 0u; *(uint32_t*)&kq2_g[po] = 0u;
    }
    if (lane == 0) { sq_g[row] = sq; sk_g[row] = sk; }
}

// ===========================================================================
// Flash attention: S-phase int8 2-digit (k32), PV bf16 3-pass. (R10 exact.)
// CTA = (q-tile 128 rows, bh), 8 warps. Double-buffered K/V. fp32 ctx out.
// ===========================================================================
#define QIP 112                          // int8 row pitch in smem (96 + 16)
#define AQ1 0                            // QI1: 128*112 = 14336
#define AQ2 14336
#define AKVQ 28672
#define SK1o 0
#define SK2o 7168
#define SVHo 14336
#define SVLo 25600
#define SSKo 36864                       // 64 floats
#define KVSTG 37120
#define ATTN_SMEM (AKVQ + 2*KVSTG)       // 102912
#define APITCH 176                       // bf16 V row pitch

__global__ void __launch_bounds__(256) attn_tc()
{
    extern __shared__ char dsm_raw[];
    const uint32_t base = s2u(dsm_raw);

    const int tid = threadIdx.x;
    const int w = tid >> 5, lane = tid & 31;
    const int qt = blockIdx.x, bh = blockIdx.y;
    const int b = bh >> 4, h = bh & 15;
    const float scale = 0.11180339887498948f;  // 1/sqrt(80)

    const size_t row0 = (size_t)bh * SQ;
    const size_t qrow0 = row0 + qt * 128;

    auto ISSUE_KV = [&](int kt) {
        const uint32_t sb = base + AKVQ + (kt & 1) * KVSTG;
        const size_t kr = row0 + kt * 64;
        #pragma unroll
        for (int j = 0; j < 9; j++) {
            const int idx = tid + 256 * j;        // 0..2063 used
            if (idx < 384) {
                const int r = idx / 6, c = idx - r * 6;
                cpasync16(sb + SK1o + r * QIP + c * 16,
                          kq1_g + (kr + r) * QPAD + c * 16);
            } else if (idx < 768) {
                const int l = idx - 384, r = l / 6, c = l - r * 6;
                cpasync16(sb + SK2o + r * QIP + c * 16,
                          kq2_g + (kr + r) * QPAD + c * 16);
            } else if (idx < 1408) {
                const int l = idx - 768, r = l / 10, c = l - r * 10;
                cpasync16(sb + SVHo + r * APITCH + c * 16,
                          vh_g + (kr + r) * HD + c * 8);
            } else if (idx < 2048) {
                const int l = idx - 1408, r = l / 10, c = l - r * 10;
                cpasync16(sb + SVLo + r * APITCH + c * 16,
                          vl_g + (kr + r) * HD + c * 8);
            } else if (idx < 2064) {
                const int l = idx - 2048;
                cpasync16(sb + SSKo + l * 16, sk_g + kr + l * 4);
            }
        }
        CP_COMMIT();
    };

    // Q int8 tiles (once): 128 rows x 6 chunks x 2 mats = 1536
    {
        #pragma unroll
        for (int j = 0; j < 6; j++) {
            const int idx = tid + 256 * j;
            const int mat = idx / 768;
            const int rem = idx - mat * 768;
            const int r = rem / 6, c = rem - r * 6;
            cpasync16(base + (mat ? AQ2 : AQ1) + r * QIP + c * 16,
                      (mat ? qq2_g : qq1_g) + (qrow0 + r) * QPAD + c * 16);
        }
        CP_COMMIT();
    }
    ISSUE_KV(0);

    const float sq0 = sq_g[qrow0 + w*16 + (lane >> 2)];
    const float sq1 = sq_g[qrow0 + w*16 + (lane >> 2) + 8];

    float oacc[10][4];
    #pragma unroll
    for (int i = 0; i < 10; i++)
        #pragma unroll
        for (int j = 0; j < 4; j++) oacc[i][j] = 0.f;
    float m0 = -1e30f, m1 = -1e30f, l0 = 0.f, l1 = 0.f;

    for (int kt = 0; kt < 16; kt++) {
        if (kt + 1 < 16) { ISSUE_KV(kt + 1); CP_WAIT1(); } else { CP_WAIT0(); }
        __syncthreads();

        const uint32_t kvb = base + AKVQ + (kt & 1) * KVSTG;
        const float* skf = (const float*)(dsm_raw + AKVQ + (kt & 1) * KVSTG + SSKo);

        // ---- S = Q K^T, int8 2-digit (3 k-chunks x 3 passes) ----
        int accP[8][4], accX[8][4];
        #pragma unroll
        for (int i = 0; i < 8; i++)
            #pragma unroll
            for (int j = 0; j < 4; j++) { accP[i][j] = 0; accX[i][j] = 0; }

        #pragma unroll
        for (int kc = 0; kc < 3; kc++) {
            uint32_t Ad1[4], Ad2[4];
            const uint32_t aoff =
                (uint32_t)((w*16 + (lane & 15)) * QIP + kc*32 + (lane >> 4) * 16);
            ldm_x4(Ad1, base + AQ1 + aoff);
            ldm_x4(Ad2, base + AQ2 + aoff);
            uint32_t Bd1[4][4], Bd2[4][4];
            #pragma unroll
            for (int g = 0; g < 4; g++) {
                const int quad = lane >> 3;
                const uint32_t boff =
                    (uint32_t)((g*16 + (quad >> 1) * 8 + (lane & 7)) * QIP
                               + kc*32 + (quad & 1) * 16);
                ldm_x4(Bd1[g], kvb + SK1o + boff);
                ldm_x4(Bd2[g], kvb + SK2o + boff);
            }
            #pragma unroll
            for (int nb = 0; nb < 8; nb++)
                mma_s8(accP[nb], Ad1, Bd1[nb>>1][(nb&1)*2], Bd1[nb>>1][(nb&1)*2+1]);
            #pragma unroll
            for (int nb = 0; nb < 8; nb++)
                mma_s8(accX[nb], Ad1, Bd2[nb>>1][(nb&1)*2], Bd2[nb>>1][(nb&1)*2+1]);
            #pragma unroll
            for (int nb = 0; nb < 8; nb++)
                mma_s8(accX[nb], Ad2, Bd1[nb>>1][(nb&1)*2], Bd1[nb>>1][(nb&1)*2+1]);
        }

        // ---- reconstruct scores + online softmax ----
        float sacc[8][4];
        #pragma unroll
        for (int nb = 0; nb < 8; nb++) {
            const int col = nb*8 + (lane & 3) * 2;
            const float k0 = skf[col] * scale, k1 = skf[col + 1] * scale;
            sacc[nb][0] = sq0 * k0 * ((float)accP[nb][0] + (float)accX[nb][0] * 0.004f);
            sacc[nb][1] = sq0 * k1 * ((float)accP[nb][1] + (float)accX[nb][1] * 0.004f);
            sacc[nb][2] = sq1 * k0 * ((float)accP[nb][2] + (float)accX[nb][2] * 0.004f);
            sacc[nb][3] = sq1 * k1 * ((float)accP[nb][3] + (float)accX[nb][3] * 0.004f);
        }

        float mx0 = -1e30f, mx1 = -1e30f;
        #pragma unroll
        for (int nb = 0; nb < 8; nb++) {
            mx0 = fmaxf(mx0, fmaxf(sacc[nb][0], sacc[nb][1]));
            mx1 = fmaxf(mx1, fmaxf(sacc[nb][2], sacc[nb][3]));
        }
        mx0 = fmaxf(mx0, __shfl_xor_sync(0xffffffffu, mx0, 1));
        mx0 = fmaxf(mx0, __shfl_xor_sync(0xffffffffu, mx0, 2));
        mx1 = fmaxf(mx1, __shfl_xor_sync(0xffffffffu, mx1, 1));
        mx1 = fmaxf(mx1, __shfl_xor_sync(0xffffffffu, mx1, 2));

        const float mn0 = fmaxf(m0, mx0), mn1 = fmaxf(m1, mx1);
        const float al0 = __expf(m0 - mn0), al1 = __expf(m1 - mn1);
        m0 = mn0; m1 = mn1;

        float rs0 = 0.f, rs1 = 0.f;
        #pragma unroll
        for (int nb = 0; nb < 8; nb++) {
            sacc[nb][0] = __expf(sacc[nb][0] - m0);
            sacc[nb][1] = __expf(sacc[nb][1] - m0);
            sacc[nb][2] = __expf(sacc[nb][2] - m1);
            sacc[nb][3] = __expf(sacc[nb][3] - m1);
            rs0 += sacc[nb][0] + sacc[nb][1];
            rs1 += sacc[nb][2] + sacc[nb][3];
        }
        rs0 += __shfl_xor_sync(0xffffffffu, rs0, 1);
        rs0 += __shfl_xor_sync(0xffffffffu, rs0, 2);
        rs1 += __shfl_xor_sync(0xffffffffu, rs1, 1);
        rs1 += __shfl_xor_sync(0xffffffffu, rs1, 2);
        l0 = l0 * al0 + rs0;
        l1 = l1 * al1 + rs1;

        #pragma unroll
        for (int nb = 0; nb < 10; nb++) {
            oacc[nb][0] *= al0; oacc[nb][1] *= al0;
            oacc[nb][2] *= al1; oacc[nb][3] *= al1;
        }

        // ---- O += P @ V, bf16 3-pass ----
        #pragma unroll
        for (int kc = 0; kc < 4; kc++) {
            uint32_t Pa_h[4], Pa_l[4];
            #pragma unroll
            for (int half2i = 0; half2i < 2; half2i++) {
                const int nb = 2*kc + half2i;
                float f0 = sacc[nb][0], f1 = sacc[nb][1];
                float f2 = sacc[nb][2], f3 = sacc[nb][3];
                float h0 = __bfloat162float(__float2bfloat16_rn(f0));
                float h1 = __bfloat162float(__float2bfloat16_rn(f1));
                float h2 = __bfloat162float(__float2bfloat16_rn(f2));
                float h3 = __bfloat162float(__float2bfloat16_rn(f3));
                Pa_h[2*half2i+0] = packbf(h0, h1);
                Pa_h[2*half2i+1] = packbf(h2, h3);
                Pa_l[2*half2i+0] = packbf(f0 - h0, f1 - h1);
                Pa_l[2*half2i+1] = packbf(f2 - h2, f3 - h3);
            }
            uint32_t Vh4[5][4], Vl4[5][4];
            #pragma unroll
            for (int vg = 0; vg < 5; vg++) {
                const int vrow = kc*16 + ((lane >> 3) & 1) * 8 + (lane & 7);
                const int vcol = vg*16 + (lane >> 4) * 8;
                const uint32_t voff = (uint32_t)(vrow * APITCH + vcol * 2);
                ldm_x4_t(Vh4[vg], kvb + SVHo + voff);
                ldm_x4_t(Vl4[vg], kvb + SVLo + voff);
            }
            #pragma unroll
            for (int vg = 0; vg < 5; vg++)
                #pragma unroll
                for (int hh = 0; hh < 2; hh++)
                    mma16816(oacc[vg*2+hh], Pa_h, Vh4[vg][2*hh], Vh4[vg][2*hh+1]);
            #pragma unroll
            for (int vg = 0; vg < 5; vg++)
                #pragma unroll
                for (int hh = 0; hh < 2; hh++)
                    mma16816(oacc[vg*2+hh], Pa_l, Vh4[vg][2*hh], Vh4[vg][2*hh+1]);
            #pragma unroll
            for (int vg = 0; vg < 5; vg++)
                #pragma unroll
                for (int hh = 0; hh < 2; hh++)
                    mma16816(oacc[vg*2+hh], Pa_h, Vl4[vg][2*hh], Vl4[vg][2*hh+1]);
        }
        __syncthreads();
    }

    // ---- finalize: normalize, write fp32 ctx ----
    const float inv0 = 1.f / l0, inv1 = 1.f / l1;
    const int s0 = qt*128 + w*16 + (lane >> 2);
    const int s1 = s0 + 8;
    #pragma unroll
    for (int nb = 0; nb < 10; nb++) {
        const int d = nb*8 + (lane & 3) * 2;
        {
            float2 v; v.x = oacc[nb][0] * inv0; v.y = oacc[nb][1] * inv0;
            *(float2*)&g_ctx[((size_t)b * SQ + s0) * DM + h * HD + d] = v;
        }
        {
            float2 v; v.x = oacc[nb][2] * inv1; v.y = oacc[nb][3] * inv1;
            *(float2*)&g_ctx[((size_t)b * SQ + s1) * DM + h * HD + d] = v;
        }
    }
}

// ---------------------------------------------------------------------------
extern "C" void kernel_launch(void* const* d_in, const int* in_sizes, int n_in,
                              void* d_out, int out_size)
{
    (void)in_sizes; (void)n_in; (void)out_size;
    const float* x     = (const float*)d_in[0];
    const float* cosp  = (const float*)d_in[1];
    const float* sinp  = (const float*)d_in[2];
    const float* Wqkv  = (const float*)d_in[3];
    const float* bqkv  = (const float*)d_in[4];
    const float* Wproj = (const float*)d_in[5];
    const float* bproj = (const float*)d_in[6];
    float* out = (float*)d_out;

    cudaFuncSetAttribute(gemm_i8<false>,
                         cudaFuncAttributeMaxDynamicSharedMemorySize, IGEMM_DSMEM);
    cudaFuncSetAttribute(gemm_i8<true>,
                         cudaFuncAttributeMaxDynamicSharedMemorySize, IGEMM_DSMEM);
    cudaFuncSetAttribute(attn_tc,
                         cudaFuncAttributeMaxDynamicSharedMemorySize, ATTN_SMEM);

    int8_t *xq1, *xq2, *wq1, *wq2;
    float *sax, *sbw, *ctx;
    cudaGetSymbolAddress((void**)&xq1, xq1_g);
    cudaGetSymbolAddress((void**)&xq2, xq2_g);
    cudaGetSymbolAddress((void**)&wq1, wq1_g);
    cudaGetSymbolAddress((void**)&wq2, wq2_g);
    cudaGetSymbolAddress((void**)&sax, sax_g);
    cudaGetSymbolAddress((void**)&sbw, sbw_g);
    cudaGetSymbolAddress((void**)&ctx, g_ctx);

    // 0) fused quantize: x + Wqkv
    quant2_kernel<<<MTOT + NQKV, 128>>>(x, xq1, xq2, sax, MTOT,
                                        Wqkv, wq1, wq2, sbw);
    // 1) QKV GEMM (int8): q,k fp32 head-major + v bf16 hi/lo
    gemm_i8<false><<<dim3(NQKV/64, MTOT/128), 256, IGEMM_DSMEM>>>(
        xq1, xq2, wq1, wq2, sax, sbw, bqkv, nullptr);
    // 2) RoPE + int8 quant -> qq/kq + scales (vectorized)
    rope_quant<<<NROWS/8, 256>>>(cosp, sinp);
    // 3) attention (int8 S, bf16 PV) -> fp32 ctx
    attn_tc<<<dim3(SQ/128, NB*NH), 256, ATTN_SMEM>>>();
    // 4) fused quantize: ctx + Wproj (reusing digit buffers)
    quant2_kernel<<<MTOT + DM, 128>>>(ctx, xq1, xq2, sax, MTOT,
                                      Wproj, wq1, wq2, sbw);
    // 5) output projection (int8) -> d_out
    gemm_i8<true><<<dim3(DM/64, MTOT/128), 256, IGEMM_DSMEM>>>(
        xq1, xq2, wq1, wq2, sax, sbw, bproj, out);
}

// round 15
// speedup vs baseline: 1.2077x; 1.0244x over previous
#include <cuda_runtime.h>
#include <cuda_bf16.h>
#include <cstdint>

#define NB 4
#define SQ 1024
#define DM 1280
#define NH 16
#define HD 80
#define MTOT (NB*SQ)      // 4096
#define NQKV (3*DM)       // 3840
#define NROWS (NB*NH*SQ)  // 65536
#define QPAD 96           // int8 q/k rows padded 80 -> 96

// ---------------------------------------------------------------------------
// Scratch (__device__ globals; allocation-free rule)
// ---------------------------------------------------------------------------
__device__ float g_q[NROWS*HD];
__device__ float g_k[NROWS*HD];
__device__ float g_ctx[MTOT*DM];

// int8 2-digit operands (xq*/sax reused for ctx; wq*/sbw reused for Wproj)
__device__ int8_t xq1_g[MTOT*DM],  xq2_g[MTOT*DM];
__device__ int8_t wq1_g[NQKV*DM],  wq2_g[NQKV*DM];
__device__ float  sax_g[MTOT];
__device__ float  sbw_g[NQKV];

// int8 2-digit rotated q/k + per-row scales
__device__ int8_t qq1_g[NROWS*QPAD], qq2_g[NROWS*QPAD];
__device__ int8_t kq1_g[NROWS*QPAD], kq2_g[NROWS*QPAD];
__device__ float  sq_g[NROWS], sk_g[NROWS];

// bf16 hi/lo V (PV stays bf16)
__device__ __nv_bfloat16 vh_g[NROWS*HD], vl_g[NROWS*HD];

// ---------------------------------------------------------------------------
// helpers
// ---------------------------------------------------------------------------
__device__ __forceinline__ uint32_t s2u(const void* p) {
    uint32_t a;
    asm("{ .reg .u64 t; cvta.to.shared.u64 t, %1; cvt.u32.u64 %0, t; }"
        : "=r"(a) : "l"(p));
    return a;
}
__device__ __forceinline__ void ldm_x4(uint32_t* r, uint32_t addr) {
    asm volatile("ldmatrix.sync.aligned.m8n8.x4.shared.b16 {%0,%1,%2,%3}, [%4];"
        : "=r"(r[0]), "=r"(r[1]), "=r"(r[2]), "=r"(r[3]) : "r"(addr));
}
__device__ __forceinline__ void ldm_x4_t(uint32_t* r, uint32_t addr) {
    asm volatile("ldmatrix.sync.aligned.m8n8.x4.trans.shared.b16 {%0,%1,%2,%3}, [%4];"
        : "=r"(r[0]), "=r"(r[1]), "=r"(r[2]), "=r"(r[3]) : "r"(addr));
}
__device__ __forceinline__ void mma16816(float* c, const uint32_t* a,
                                         uint32_t b0, uint32_t b1) {
    asm volatile(
        "mma.sync.aligned.m16n8k16.row.col.f32.bf16.bf16.f32 "
        "{%0,%1,%2,%3}, {%4,%5,%6,%7}, {%8,%9}, {%0,%1,%2,%3};"
        : "+f"(c[0]), "+f"(c[1]), "+f"(c[2]), "+f"(c[3])
        : "r"(a[0]), "r"(a[1]), "r"(a[2]), "r"(a[3]), "r"(b0), "r"(b1));
}
__device__ __forceinline__ void mma_s8(int* c, const uint32_t* a,
                                       uint32_t b0, uint32_t b1) {
    asm volatile(
        "mma.sync.aligned.m16n8k32.row.col.s32.s8.s8.s32 "
        "{%0,%1,%2,%3}, {%4,%5,%6,%7}, {%8,%9}, {%0,%1,%2,%3};"
        : "+r"(c[0]), "+r"(c[1]), "+r"(c[2]), "+r"(c[3])
        : "r"(a[0]), "r"(a[1]), "r"(a[2]), "r"(a[3]), "r"(b0), "r"(b1));
}
__device__ __forceinline__ uint32_t packbf(float a, float b) {
    __nv_bfloat162 t = __floats2bfloat162_rn(a, b);
    return *reinterpret_cast<uint32_t*>(&t);
}
__device__ __forceinline__ void cpasync16(uint32_t dst, const void* src) {
    asm volatile("cp.async.ca.shared.global [%0], [%1], 16;"
        :: "r"(dst), "l"(src) : "memory");
}
#define CP_COMMIT() asm volatile("cp.async.commit_group;" ::: "memory")
#define CP_WAIT0()  asm volatile("cp.async.wait_group 0;" ::: "memory")
#define CP_WAIT1()  asm volatile("cp.async.wait_group 1;" ::: "memory")

// ---------------------------------------------------------------------------
// Fused fp32 -> int8 2-digit row quantization for TWO tensors (same DM cols).
// v = s*(d1 + d2/250), s = rowmax/120. One 128-thr block per row.
// ---------------------------------------------------------------------------
__global__ void __launch_bounds__(128) quant2_kernel(
    const float* __restrict__ s0, int8_t* __restrict__ a1,
    int8_t* __restrict__ a2, float* __restrict__ sc0, int n0,
    const float* __restrict__ s1, int8_t* __restrict__ b1,
    int8_t* __restrict__ b2, float* __restrict__ sc1)
{
    const int bid = blockIdx.x;
    const float* src; int8_t* d1; int8_t* d2; float* scale; int row;
    if (bid < n0) { src = s0; d1 = a1; d2 = a2; scale = sc0; row = bid; }
    else          { src = s1; d1 = b1; d2 = b2; scale = sc1; row = bid - n0; }

    const int tid = threadIdx.x;
    const float* p = src + (size_t)row * DM;
    float mx = 0.f;
    for (int i = tid; i < DM; i += 128) mx = fmaxf(mx, fabsf(p[i]));
    #pragma unroll
    for (int off = 16; off >= 1; off >>= 1)
        mx = fmaxf(mx, __shfl_xor_sync(0xffffffffu, mx, off));
    __shared__ float smx[4];
    if ((tid & 31) == 0) smx[tid >> 5] = mx;
    __syncthreads();
    mx = fmaxf(fmaxf(smx[0], smx[1]), fmaxf(smx[2], smx[3]));
    const float s = (mx > 0.f) ? mx * (1.f / 120.f) : 1.f;
    const float inv = 1.f / s;
    for (int i = tid; i < DM; i += 128) {
        const float f  = p[i] * inv;
        const float q1 = rintf(f);
        const float q2 = rintf(250.f * (f - q1));
        d1[(size_t)row * DM + i] = (int8_t)(int)q1;
        d2[(size_t)row * DM + i] = (int8_t)(int)q2;
    }
    if (tid == 0) scale[row] = s;
}

// ===========================================================================
// int8 2-digit GEMM core (R10 exact): C = sa[m]*sb[n]*(P + X/250) + bias[n].
// CTA 128(M)x64(N), 256 thr, 8 warps of 32x32, K-stage 128 int8, 2-stage.
// PROJ=false: QKV (scatter q,k fp32 + v bf16 hi/lo). PROJ=true: dense out.
// ===========================================================================
#define IK 128
#define IPITCH 144
#define IOFF_A2 (128*IPITCH)
#define IOFF_B1 (2*128*IPITCH)
#define IOFF_B2 (IOFF_B1 + 64*IPITCH)
#define ISTAGE (IOFF_B2 + 64*IPITCH)
#define IGEMM_DSMEM (2*ISTAGE)         // 110592

template<bool PROJ>
__global__ void __launch_bounds__(256, 2) gemm_i8(
    const int8_t* __restrict__ A1, const int8_t* __restrict__ A2,
    const int8_t* __restrict__ B1, const int8_t* __restrict__ B2,
    const float* __restrict__ sa_v, const float* __restrict__ sb_v,
    const float* __restrict__ bias, float* __restrict__ Cout)
{
    extern __shared__ char dsm_raw[];
    const uint32_t base = s2u(dsm_raw);

    const int tid  = threadIdx.x;
    const int wid  = tid >> 5, lane = tid & 31;
    const int bx = blockIdx.x, by = blockIdx.y;
    const int wm = wid >> 1, wn = wid & 1;    // warp tile 32(M) x 32(N)

    const int8_t* a1p = A1 + (size_t)(by * 128) * DM;
    const int8_t* a2p = A2 + (size_t)(by * 128) * DM;
    const int8_t* b1p = B1 + (size_t)(bx * 64) * DM;
    const int8_t* b2p = B2 + (size_t)(bx * 64) * DM;

    auto ISSUE = [&](int it) {
        const uint32_t sb = base + (it & 1) * ISTAGE;
        const int kof = it * IK;
        #pragma unroll
        for (int j = 0; j < 12; j++) {
            const int idx = tid + 256 * j;
            int local; uint32_t moff; const int8_t* srcp;
            if (j < 4)       { local = idx;        moff = 0;       srcp = a1p; }
            else if (j < 8)  { local = idx - 1024; moff = IOFF_A2; srcp = a2p; }
            else if (j < 10) { local = idx - 2048; moff = IOFF_B1; srcp = b1p; }
            else             { local = idx - 2560; moff = IOFF_B2; srcp = b2p; }
            const int r = local >> 3, c = local & 7;
            cpasync16(sb + moff + r * IPITCH + c * 16,
                      srcp + (size_t)r * DM + kof + c * 16);
        }
        CP_COMMIT();
    };

    int accP[2][4][4], accX[2][4][4];
    #pragma unroll
    for (int i = 0; i < 2; i++)
        #pragma unroll
        for (int j = 0; j < 4; j++)
            #pragma unroll
            for (int q = 0; q < 4; q++) { accP[i][j][q] = 0; accX[i][j][q] = 0; }

    ISSUE(0); ISSUE(1);

    const int NITI = DM / IK;
    for (int it = 0; it < NITI; ++it) {
        if (it == NITI - 1) { CP_WAIT0(); } else { CP_WAIT1(); }
        __syncthreads();

        const uint32_t sb = base + (it & 1) * ISTAGE;
        #pragma unroll
        for (int kc = 0; kc < 4; kc++) {
            uint32_t Ad1[2][4], Ad2[2][4];
            #pragma unroll
            for (int mf = 0; mf < 2; mf++) {
                const uint32_t aoff =
                    (uint32_t)((wm*32 + mf*16 + (lane & 15)) * IPITCH
                               + kc*32 + (lane >> 4) * 16);
                ldm_x4(Ad1[mf], sb + aoff);
                ldm_x4(Ad2[mf], sb + IOFF_A2 + aoff);
            }
            uint32_t Bd1[2][4], Bd2[2][4];
            #pragma unroll
            for (int g = 0; g < 2; g++) {
                const int quad = lane >> 3;
                const uint32_t boff =
                    (uint32_t)((wn*32 + g*16 + (quad >> 1) * 8 + (lane & 7)) * IPITCH
                               + kc*32 + (quad & 1) * 16);
                ldm_x4(Bd1[g], sb + IOFF_B1 + boff);
                ldm_x4(Bd2[g], sb + IOFF_B2 + boff);
            }
            #pragma unroll
            for (int mf = 0; mf < 2; mf++)
                #pragma unroll
                for (int nb = 0; nb < 4; nb++)
                    mma_s8(accP[mf][nb], Ad1[mf], Bd1[nb>>1][(nb&1)*2], Bd1[nb>>1][(nb&1)*2+1]);
            #pragma unroll
            for (int mf = 0; mf < 2; mf++)
                #pragma unroll
                for (int nb = 0; nb < 4; nb++)
                    mma_s8(accX[mf][nb], Ad1[mf], Bd2[nb>>1][(nb&1)*2], Bd2[nb>>1][(nb&1)*2+1]);
            #pragma unroll
            for (int mf = 0; mf < 2; mf++)
                #pragma unroll
                for (int nb = 0; nb < 4; nb++)
                    mma_s8(accX[mf][nb], Ad2[mf], Bd1[nb>>1][(nb&1)*2], Bd1[nb>>1][(nb&1)*2+1]);
        }
        __syncthreads();
        if (it + 2 < NITI) ISSUE(it + 2);
    }

    #pragma unroll
    for (int mf = 0; mf < 2; mf++)
        #pragma unroll
        for (int nb = 0; nb < 4; nb++)
            #pragma unroll
            for (int ci = 0; ci < 2; ci++) {
                const int m = by*128 + wm*32 + mf*16 + (lane >> 2) + ci*8;
                const int n = bx*64 + wn*32 + nb*8 + (lane & 3) * 2;
                const float sa = sa_v[m];
                float2 v;
                v.x = sa * sb_v[n]   * ((float)accP[mf][nb][2*ci+0]
                        + (float)accX[mf][nb][2*ci+0] * 0.004f) + bias[n];
                v.y = sa * sb_v[n+1] * ((float)accP[mf][nb][2*ci+1]
                        + (float)accX[mf][nb][2*ci+1] * 0.004f) + bias[n+1];
                if (PROJ) {
                    *(float2*)&Cout[(size_t)m * DM + n] = v;
                } else {
                    const int sel = n / DM;
                    const int r2  = n - sel * DM;
                    const int h   = r2 / HD;
                    const int dd  = r2 - h * HD;
                    const int bb  = m >> 10;
                    const int ss  = m & (SQ - 1);
                    const size_t di = (((size_t)bb * NH + h) * SQ + ss) * HD + dd;
                    if (sel == 0)      *(float2*)&g_q[di] = v;
                    else if (sel == 1) *(float2*)&g_k[di] = v;
                    else {
                        __nv_bfloat16 h0 = __float2bfloat16_rn(v.x);
                        __nv_bfloat16 h1 = __float2bfloat16_rn(v.y);
                        *(__nv_bfloat162*)&vh_g[di] = __nv_bfloat162(h0, h1);
                        *(__nv_bfloat162*)&vl_g[di] = __floats2bfloat162_rn(
                            v.x - __bfloat162float(h0), v.y - __bfloat162float(h1));
                    }
                }
            }
}

// ---------------------------------------------------------------------------
// RoPE + int8 2-digit quantization, vectorized. One warp per (b,h,s) row.
// ---------------------------------------------------------------------------
__global__ void __launch_bounds__(256) rope_quant(
    const float* __restrict__ cosp, const float* __restrict__ sinp)
{
    const int row  = (blockIdx.x << 3) + (threadIdx.x >> 5);   // < NROWS
    const int lane = threadIdx.x & 31;
    const int ss   = row & (SQ - 1);
    const size_t base = (size_t)row * HD;
    const size_t rb   = (size_t)row * QPAD;

    const bool isQ = lane < 10;
    const bool isK = lane >= 10 && lane < 20;
    const int  i4  = isQ ? lane : (lane - 10);   // 0..9
    const int  d   = i4 * 4;

    float lo[4], hi[4];
    float m = 0.f;
    if (isQ || isK) {
        const float* t = isQ ? g_q : g_k;
        const float4 ta = *(const float4*)&t[base + d];
        const float4 tb = *(const float4*)&t[base + d + 40];
        const float4 ca = *(const float4*)&cosp[ss*HD + d];
        const float4 cb = *(const float4*)&cosp[ss*HD + d + 40];
        const float4 sa = *(const float4*)&sinp[ss*HD + d];
        const float4 sb = *(const float4*)&sinp[ss*HD + d + 40];
        lo[0] = ta.x*ca.x - tb.x*sa.x;  hi[0] = tb.x*cb.x + ta.x*sb.x;
        lo[1] = ta.y*ca.y - tb.y*sa.y;  hi[1] = tb.y*cb.y + ta.y*sb.y;
        lo[2] = ta.z*ca.z - tb.z*sa.z;  hi[2] = tb.z*cb.z + ta.z*sb.z;
        lo[3] = ta.w*ca.w - tb.w*sa.w;  hi[3] = tb.w*cb.w + ta.w*sb.w;
        #pragma unroll
        for (int e = 0; e < 4; e++)
            m = fmaxf(m, fmaxf(fabsf(lo[e]), fabsf(hi[e])));
    }

    float qm = isQ ? m : 0.f;
    float km = isK ? m : 0.f;
    #pragma unroll
    for (int off = 16; off >= 1; off >>= 1) {
        qm = fmaxf(qm, __shfl_xor_sync(0xffffffffu, qm, off));
        km = fmaxf(km, __shfl_xor_sync(0xffffffffu, km, off));
    }
    const float sq = (qm > 0.f) ? qm * (1.f/120.f) : 1.f;
    const float sk = (km > 0.f) ? km * (1.f/120.f) : 1.f;

    if (isQ || isK) {
        const float inv = isQ ? (1.f / sq) : (1.f / sk);
        int8_t* o1 = isQ ? qq1_g : kq1_g;
        int8_t* o2 = isQ ? qq2_g : kq2_g;
        uint32_t w1lo = 0, w2lo = 0, w1hi = 0, w2hi = 0;
        #pragma unroll
        for (int e = 0; e < 4; e++) {
            float f  = lo[e] * inv;
            float q1 = rintf(f);
            int   i1 = (int)q1;
            int   i2 = (int)rintf(250.f * (f - q1));
            w1lo |= (uint32_t)(i1 & 0xFF) << (8 * e);
            w2lo |= (uint32_t)(i2 & 0xFF) << (8 * e);
            f  = hi[e] * inv;
            q1 = rintf(f);
            i1 = (int)q1;
            i2 = (int)rintf(250.f * (f - q1));
            w1hi |= (uint32_t)(i1 & 0xFF) << (8 * e);
            w2hi |= (uint32_t)(i2 & 0xFF) << (8 * e);
        }
        *(uint32_t*)&o1[rb + d]      = w1lo;
        *(uint32_t*)&o2[rb + d]      = w2lo;
        *(uint32_t*)&o1[rb + d + 40] = w1hi;
        *(uint32_t*)&o2[rb + d + 40] = w2hi;
    } else if (lane < 24) {
        const size_t po = rb + 80 + (lane - 20) * 4;
        *(uint32_t*)&qq1_g[po] = 0u; *(uint32_t*)&qq2_g[po] = 0u;
        *(uint32_t*)&kq1_g[po] = 0u; *(uint32_t*)&kq2_g[po] = 0u;
    }
    if (lane == 0) { sq_g[row] = sq; sk_g[row] = sk; }
}

// ===========================================================================
// Flash attention: S-phase int8 2-digit, PV bf16 3-pass.
// CTA = (q-tile 64 rows, bh), 4 warps (128 thr) -> 2 CTAs/SM overlap.
// Per-warp code identical to R10/R14 (16 q-rows per warp).
// ===========================================================================
#define QIP 112                          // int8 row pitch in smem (96 + 16)
#define AQ1 0                            // Q digit 1: 64*112 = 7168
#define AQ2 7168
#define AKVQ 14336
#define SK1o 0
#define SK2o 7168
#define SVHo 14336
#define SVLo 25600
#define SSKo 36864                       // 64 floats
#define KVSTG 37120
#define ATTN_SMEM (AKVQ + 2*KVSTG)       // 88576
#define APITCH 176                       // bf16 V row pitch

__global__ void __launch_bounds__(128, 2) attn_tc()
{
    extern __shared__ char dsm_raw[];
    const uint32_t base = s2u(dsm_raw);

    const int tid = threadIdx.x;
    const int w = tid >> 5, lane = tid & 31;
    const int qt = blockIdx.x, bh = blockIdx.y;
    const int b = bh >> 4, h = bh & 15;
    const float scale = 0.11180339887498948f;  // 1/sqrt(80)

    const size_t row0 = (size_t)bh * SQ;
    const size_t qrow0 = row0 + qt * 64;

    auto ISSUE_KV = [&](int kt) {
        const uint32_t sb = base + AKVQ + (kt & 1) * KVSTG;
        const size_t kr = row0 + kt * 64;
        #pragma unroll
        for (int j = 0; j < 17; j++) {
            const int idx = tid + 128 * j;        // 0..2063 used
            if (idx < 384) {
                const int r = idx / 6, c = idx - r * 6;
                cpasync16(sb + SK1o + r * QIP + c * 16,
                          kq1_g + (kr + r) * QPAD + c * 16);
            } else if (idx < 768) {
                const int l = idx - 384, r = l / 6, c = l - r * 6;
                cpasync16(sb + SK2o + r * QIP + c * 16,
                          kq2_g + (kr + r) * QPAD + c * 16);
            } else if (idx < 1408) {
                const int l = idx - 768, r = l / 10, c = l - r * 10;
                cpasync16(sb + SVHo + r * APITCH + c * 16,
                          vh_g + (kr + r) * HD + c * 8);
            } else if (idx < 2048) {
                const int l = idx - 1408, r = l / 10, c = l - r * 10;
                cpasync16(sb + SVLo + r * APITCH + c * 16,
                          vl_g + (kr + r) * HD + c * 8);
            } else if (idx < 2064) {
                const int l = idx - 2048;
                cpasync16(sb + SSKo + l * 16, sk_g + kr + l * 4);
            }
        }
        CP_COMMIT();
    };

    // Q int8 tiles (once): 64 rows x 6 chunks x 2 mats = 768
    {
        #pragma unroll
        for (int j = 0; j < 6; j++) {
            const int idx = tid + 128 * j;
            const int mat = idx / 384;
            const int rem = idx - mat * 384;
            const int r = rem / 6, c = rem - r * 6;
            cpasync16(base + (mat ? AQ2 : AQ1) + r * QIP + c * 16,
                      (mat ? qq2_g : qq1_g) + (qrow0 + r) * QPAD + c * 16);
        }
        CP_COMMIT();
    }
    ISSUE_KV(0);

    const float sq0 = sq_g[qrow0 + w*16 + (lane >> 2)];
    const float sq1 = sq_g[qrow0 + w*16 + (lane >> 2) + 8];

    float oacc[10][4];
    #pragma unroll
    for (int i = 0; i < 10; i++)
        #pragma unroll
        for (int j = 0; j < 4; j++) oacc[i][j] = 0.f;
    float m0 = -1e30f, m1 = -1e30f, l0 = 0.f, l1 = 0.f;

    for (int kt = 0; kt < 16; kt++) {
        if (kt + 1 < 16) { ISSUE_KV(kt + 1); CP_WAIT1(); } else { CP_WAIT0(); }
        __syncthreads();

        const uint32_t kvb = base + AKVQ + (kt & 1) * KVSTG;
        const float* skf = (const float*)(dsm_raw + AKVQ + (kt & 1) * KVSTG + SSKo);

        // ---- S = Q K^T, int8 2-digit (3 k-chunks x 3 passes) ----
        int accP[8][4], accX[8][4];
        #pragma unroll
        for (int i = 0; i < 8; i++)
            #pragma unroll
            for (int j = 0; j < 4; j++) { accP[i][j] = 0; accX[i][j] = 0; }

        #pragma unroll
        for (int kc = 0; kc < 3; kc++) {
            uint32_t Ad1[4], Ad2[4];
            const uint32_t aoff =
                (uint32_t)((w*16 + (lane & 15)) * QIP + kc*32 + (lane >> 4) * 16);
            ldm_x4(Ad1, base + AQ1 + aoff);
            ldm_x4(Ad2, base + AQ2 + aoff);
            uint32_t Bd1[4][4], Bd2[4][4];
            #pragma unroll
            for (int g = 0; g < 4; g++) {
                const int quad = lane >> 3;
                const uint32_t boff =
                    (uint32_t)((g*16 + (quad >> 1) * 8 + (lane & 7)) * QIP
                               + kc*32 + (quad & 1) * 16);
                ldm_x4(Bd1[g], kvb + SK1o + boff);
                ldm_x4(Bd2[g], kvb + SK2o + boff);
            }
            #pragma unroll
            for (int nb = 0; nb < 8; nb++)
                mma_s8(accP[nb], Ad1, Bd1[nb>>1][(nb&1)*2], Bd1[nb>>1][(nb&1)*2+1]);
            #pragma unroll
            for (int nb = 0; nb < 8; nb++)
                mma_s8(accX[nb], Ad1, Bd2[nb>>1][(nb&1)*2], Bd2[nb>>1][(nb&1)*2+1]);
            #pragma unroll
            for (int nb = 0; nb < 8; nb++)
                mma_s8(accX[nb], Ad2, Bd1[nb>>1][(nb&1)*2], Bd1[nb>>1][(nb&1)*2+1]);
        }

        // ---- reconstruct scores + online softmax ----
        float sacc[8][4];
        #pragma unroll
        for (int nb = 0; nb < 8; nb++) {
            const int col = nb*8 + (lane & 3) * 2;
            const float k0 = skf[col] * scale, k1 = skf[col + 1] * scale;
            sacc[nb][0] = sq0 * k0 * ((float)accP[nb][0] + (float)accX[nb][0] * 0.004f);
            sacc[nb][1] = sq0 * k1 * ((float)accP[nb][1] + (float)accX[nb][1] * 0.004f);
            sacc[nb][2] = sq1 * k0 * ((float)accP[nb][2] + (float)accX[nb][2] * 0.004f);
            sacc[nb][3] = sq1 * k1 * ((float)accP[nb][3] + (float)accX[nb][3] * 0.004f);
        }

        float mx0 = -1e30f, mx1 = -1e30f;
        #pragma unroll
        for (int nb = 0; nb < 8; nb++) {
            mx0 = fmaxf(mx0, fmaxf(sacc[nb][0], sacc[nb][1]));
            mx1 = fmaxf(mx1, fmaxf(sacc[nb][2], sacc[nb][3]));
        }
        mx0 = fmaxf(mx0, __shfl_xor_sync(0xffffffffu, mx0, 1));
        mx0 = fmaxf(mx0, __shfl_xor_sync(0xffffffffu, mx0, 2));
        mx1 = fmaxf(mx1, __shfl_xor_sync(0xffffffffu, mx1, 1));
        mx1 = fmaxf(mx1, __shfl_xor_sync(0xffffffffu, mx1, 2));

        const float mn0 = fmaxf(m0, mx0), mn1 = fmaxf(m1, mx1);
        const float al0 = __expf(m0 - mn0), al1 = __expf(m1 - mn1);
        m0 = mn0; m1 = mn1;

        float rs0 = 0.f, rs1 = 0.f;
        #pragma unroll
        for (int nb = 0; nb < 8; nb++) {
            sacc[nb][0] = __expf(sacc[nb][0] - m0);
            sacc[nb][1] = __expf(sacc[nb][1] - m0);
            sacc[nb][2] = __expf(sacc[nb][2] - m1);
            sacc[nb][3] = __expf(sacc[nb][3] - m1);
            rs0 += sacc[nb][0] + sacc[nb][1];
            rs1 += sacc[nb][2] + sacc[nb][3];
        }
        rs0 += __shfl_xor_sync(0xffffffffu, rs0, 1);
        rs0 += __shfl_xor_sync(0xffffffffu, rs0, 2);
        rs1 += __shfl_xor_sync(0xffffffffu, rs1, 1);
        rs1 += __shfl_xor_sync(0xffffffffu, rs1, 2);
        l0 = l0 * al0 + rs0;
        l1 = l1 * al1 + rs1;

        #pragma unroll
        for (int nb = 0; nb < 10; nb++) {
            oacc[nb][0] *= al0; oacc[nb][1] *= al0;
            oacc[nb][2] *= al1; oacc[nb][3] *= al1;
        }

        // ---- O += P @ V, bf16 3-pass ----
        #pragma unroll
        for (int kc = 0; kc < 4; kc++) {
            uint32_t Pa_h[4], Pa_l[4];
            #pragma unroll
            for (int half2i = 0; half2i < 2; half2i++) {
                const int nb = 2*kc + half2i;
                float f0 = sacc[nb][0], f1 = sacc[nb][1];
                float f2 = sacc[nb][2], f3 = sacc[nb][3];
                float h0 = __bfloat162float(__float2bfloat16_rn(f0));
                float h1 = __bfloat162float(__float2bfloat16_rn(f1));
                float h2 = __bfloat162float(__float2bfloat16_rn(f2));
                float h3 = __bfloat162float(__float2bfloat16_rn(f3));
                Pa_h[2*half2i+0] = packbf(h0, h1);
                Pa_h[2*half2i+1] = packbf(h2, h3);
                Pa_l[2*half2i+0] = packbf(f0 - h0, f1 - h1);
                Pa_l[2*half2i+1] = packbf(f2 - h2, f3 - h3);
            }
            uint32_t Vh4[5][4], Vl4[5][4];
            #pragma unroll
            for (int vg = 0; vg < 5; vg++) {
                const int vrow = kc*16 + ((lane >> 3) & 1) * 8 + (lane & 7);
                const int vcol = vg*16 + (lane >> 4) * 8;
                const uint32_t voff = (uint32_t)(vrow * APITCH + vcol * 2);
                ldm_x4_t(Vh4[vg], kvb + SVHo + voff);
                ldm_x4_t(Vl4[vg], kvb + SVLo + voff);
            }
            #pragma unroll
            for (int vg = 0; vg < 5; vg++)
                #pragma unroll
                for (int hh = 0; hh < 2; hh++)
                    mma16816(oacc[vg*2+hh], Pa_h, Vh4[vg][2*hh], Vh4[vg][2*hh+1]);
            #pragma unroll
            for (int vg = 0; vg < 5; vg++)
                #pragma unroll
                for (int hh = 0; hh < 2; hh++)
                    mma16816(oacc[vg*2+hh], Pa_l, Vh4[vg][2*hh], Vh4[vg][2*hh+1]);
            #pragma unroll
            for (int vg = 0; vg < 5; vg++)
                #pragma unroll
                for (int hh = 0; hh < 2; hh++)
                    mma16816(oacc[vg*2+hh], Pa_h, Vl4[vg][2*hh], Vl4[vg][2*hh+1]);
        }
        __syncthreads();
    }

    // ---- finalize: normalize, write fp32 ctx ----
    const float inv0 = 1.f / l0, inv1 = 1.f / l1;
    const int s0 = qt*64 + w*16 + (lane >> 2);
    const int s1 = s0 + 8;
    #pragma unroll
    for (int nb = 0; nb < 10; nb++) {
        const int d = nb*8 + (lane & 3) * 2;
        {
            float2 v; v.x = oacc[nb][0] * inv0; v.y = oacc[nb][1] * inv0;
            *(float2*)&g_ctx[((size_t)b * SQ + s0) * DM + h * HD + d] = v;
        }
        {
            float2 v; v.x = oacc[nb][2] * inv1; v.y = oacc[nb][3] * inv1;
            *(float2*)&g_ctx[((size_t)b * SQ + s1) * DM + h * HD + d] = v;
        }
    }
}

// ---------------------------------------------------------------------------
extern "C" void kernel_launch(void* const* d_in, const int* in_sizes, int n_in,
                              void* d_out, int out_size)
{
    (void)in_sizes; (void)n_in; (void)out_size;
    const float* x     = (const float*)d_in[0];
    const float* cosp  = (const float*)d_in[1];
    const float* sinp  = (const float*)d_in[2];
    const float* Wqkv  = (const float*)d_in[3];
    const float* bqkv  = (const float*)d_in[4];
    const float* Wproj = (const float*)d_in[5];
    const float* bproj = (const float*)d_in[6];
    float* out = (float*)d_out;

    cudaFuncSetAttribute(gemm_i8<false>,
                         cudaFuncAttributeMaxDynamicSharedMemorySize, IGEMM_DSMEM);
    cudaFuncSetAttribute(gemm_i8<true>,
                         cudaFuncAttributeMaxDynamicSharedMemorySize, IGEMM_DSMEM);
    cudaFuncSetAttribute(attn_tc,
                         cudaFuncAttributeMaxDynamicSharedMemorySize, ATTN_SMEM);

    int8_t *xq1, *xq2, *wq1, *wq2;
    float *sax, *sbw, *ctx;
    cudaGetSymbolAddress((void**)&xq1, xq1_g);
    cudaGetSymbolAddress((void**)&xq2, xq2_g);
    cudaGetSymbolAddress((void**)&wq1, wq1_g);
    cudaGetSymbolAddress((void**)&wq2, wq2_g);
    cudaGetSymbolAddress((void**)&sax, sax_g);
    cudaGetSymbolAddress((void**)&sbw, sbw_g);
    cudaGetSymbolAddress((void**)&ctx, g_ctx);

    // 0) fused quantize: x + Wqkv
    quant2_kernel<<<MTOT + NQKV, 128>>>(x, xq1, xq2, sax, MTOT,
                                        Wqkv, wq1, wq2, sbw);
    // 1) QKV GEMM (int8): q,k fp32 head-major + v bf16 hi/lo
    gemm_i8<false><<<dim3(NQKV/64, MTOT/128), 256, IGEMM_DSMEM>>>(
        xq1, xq2, wq1, wq2, sax, sbw, bqkv, nullptr);
    // 2) RoPE + int8 quant -> qq/kq + scales (vectorized)
    rope_quant<<<NROWS/8, 256>>>(cosp, sinp);
    // 3) attention (int8 S, bf16 PV; 64-row tiles, 2 CTAs/SM) -> fp32 ctx
    attn_tc<<<dim3(SQ/64, NB*NH), 128, ATTN_SMEM>>>();
    // 4) fused quantize: ctx + Wproj (reusing digit buffers)
    quant2_kernel<<<MTOT + DM, 128>>>(ctx, xq1, xq2, sax, MTOT,
                                      Wproj, wq1, wq2, sbw);
    // 5) output projection (int8) -> d_out
    gemm_i8<true><<<dim3(DM/64, MTOT/128), 256, IGEMM_DSMEM>>>(
        xq1, xq2, wq1, wq2, sax, sbw, bproj, out);
}

// round 16
// speedup vs baseline: 1.3628x; 1.1284x over previous
#include <cuda_runtime.h>
#include <cuda_bf16.h>
#include <cuda_fp16.h>
#include <cstdint>

#define NB 4
#define SQ 1024
#define DM 1280
#define NH 16
#define HD 80
#define MTOT (NB*SQ)      // 4096
#define NQKV (3*DM)       // 3840
#define NROWS (NB*NH*SQ)  // 65536
#define QPAD 96           // int8 q/k rows padded 80 -> 96

// ---------------------------------------------------------------------------
// Scratch (__device__ globals; allocation-free rule)
// ---------------------------------------------------------------------------
__device__ float g_q[NROWS*HD];
__device__ float g_k[NROWS*HD];
__device__ float g_ctx[MTOT*DM];

// int8 2-digit operands (xq*/sax reused for ctx; wq*/sbw reused for Wproj)
__device__ int8_t xq1_g[MTOT*DM],  xq2_g[MTOT*DM];
__device__ int8_t wq1_g[NQKV*DM],  wq2_g[NQKV*DM];
__device__ float  sax_g[MTOT];
__device__ float  sbw_g[NQKV];

// int8 2-digit rotated q/k + per-row scales
__device__ int8_t qq1_g[NROWS*QPAD], qq2_g[NROWS*QPAD];
__device__ int8_t kq1_g[NROWS*QPAD], kq2_g[NROWS*QPAD];
__device__ float  sq_g[NROWS], sk_g[NROWS];

// fp16 V (PV single-pass fp16)
__device__ __half vh_g[NROWS*HD];

// ---------------------------------------------------------------------------
// helpers
// ---------------------------------------------------------------------------
__device__ __forceinline__ uint32_t s2u(const void* p) {
    uint32_t a;
    asm("{ .reg .u64 t; cvta.to.shared.u64 t, %1; cvt.u32.u64 %0, t; }"
        : "=r"(a) : "l"(p));
    return a;
}
__device__ __forceinline__ void ldm_x4(uint32_t* r, uint32_t addr) {
    asm volatile("ldmatrix.sync.aligned.m8n8.x4.shared.b16 {%0,%1,%2,%3}, [%4];"
        : "=r"(r[0]), "=r"(r[1]), "=r"(r[2]), "=r"(r[3]) : "r"(addr));
}
__device__ __forceinline__ void ldm_x4_t(uint32_t* r, uint32_t addr) {
    asm volatile("ldmatrix.sync.aligned.m8n8.x4.trans.shared.b16 {%0,%1,%2,%3}, [%4];"
        : "=r"(r[0]), "=r"(r[1]), "=r"(r[2]), "=r"(r[3]) : "r"(addr));
}
__device__ __forceinline__ void mma16816h(float* c, const uint32_t* a,
                                          uint32_t b0, uint32_t b1) {
    asm volatile(
        "mma.sync.aligned.m16n8k16.row.col.f32.f16.f16.f32 "
        "{%0,%1,%2,%3}, {%4,%5,%6,%7}, {%8,%9}, {%0,%1,%2,%3};"
        : "+f"(c[0]), "+f"(c[1]), "+f"(c[2]), "+f"(c[3])
        : "r"(a[0]), "r"(a[1]), "r"(a[2]), "r"(a[3]), "r"(b0), "r"(b1));
}
__device__ __forceinline__ void mma_s8(int* c, const uint32_t* a,
                                       uint32_t b0, uint32_t b1) {
    asm volatile(
        "mma.sync.aligned.m16n8k32.row.col.s32.s8.s8.s32 "
        "{%0,%1,%2,%3}, {%4,%5,%6,%7}, {%8,%9}, {%0,%1,%2,%3};"
        : "+r"(c[0]), "+r"(c[1]), "+r"(c[2]), "+r"(c[3])
        : "r"(a[0]), "r"(a[1]), "r"(a[2]), "r"(a[3]), "r"(b0), "r"(b1));
}
__device__ __forceinline__ uint32_t packh(float a, float b) {
    __half2 t = __floats2half2_rn(a, b);
    return *reinterpret_cast<uint32_t*>(&t);
}
__device__ __forceinline__ void cpasync16(uint32_t dst, const void* src) {
    asm volatile("cp.async.ca.shared.global [%0], [%1], 16;"
        :: "r"(dst), "l"(src) : "memory");
}
#define CP_COMMIT() asm volatile("cp.async.commit_group;" ::: "memory")
#define CP_WAIT0()  asm volatile("cp.async.wait_group 0;" ::: "memory")
#define CP_WAIT1()  asm volatile("cp.async.wait_group 1;" ::: "memory")

// ---------------------------------------------------------------------------
// Fused fp32 -> int8 2-digit row quantization for TWO tensors (same DM cols).
// v = s*(d1 + d2/250), s = rowmax/120. One 128-thr block per row.
// ---------------------------------------------------------------------------
__global__ void __launch_bounds__(128) quant2_kernel(
    const float* __restrict__ s0, int8_t* __restrict__ a1,
    int8_t* __restrict__ a2, float* __restrict__ sc0, int n0,
    const float* __restrict__ s1, int8_t* __restrict__ b1,
    int8_t* __restrict__ b2, float* __restrict__ sc1)
{
    const int bid = blockIdx.x;
    const float* src; int8_t* d1; int8_t* d2; float* scale; int row;
    if (bid < n0) { src = s0; d1 = a1; d2 = a2; scale = sc0; row = bid; }
    else          { src = s1; d1 = b1; d2 = b2; scale = sc1; row = bid - n0; }

    const int tid = threadIdx.x;
    const float* p = src + (size_t)row * DM;
    float mx = 0.f;
    for (int i = tid; i < DM; i += 128) mx = fmaxf(mx, fabsf(p[i]));
    #pragma unroll
    for (int off = 16; off >= 1; off >>= 1)
        mx = fmaxf(mx, __shfl_xor_sync(0xffffffffu, mx, off));
    __shared__ float smx[4];
    if ((tid & 31) == 0) smx[tid >> 5] = mx;
    __syncthreads();
    mx = fmaxf(fmaxf(smx[0], smx[1]), fmaxf(smx[2], smx[3]));
    const float s = (mx > 0.f) ? mx * (1.f / 120.f) : 1.f;
    const float inv = 1.f / s;
    for (int i = tid; i < DM; i += 128) {
        const float f  = p[i] * inv;
        const float q1 = rintf(f);
        const float q2 = rintf(250.f * (f - q1));
        d1[(size_t)row * DM + i] = (int8_t)(int)q1;
        d2[(size_t)row * DM + i] = (int8_t)(int)q2;
    }
    if (tid == 0) scale[row] = s;
}

// ===========================================================================
// int8 2-digit GEMM core: C = sa[m]*sb[n]*(P + X/250) + bias[n].
// CTA 128(M)x64(N), 256 thr, 8 warps of 32x32, K-stage 128 int8, 2-stage.
// PROJ=false: QKV (scatter q,k fp32 + v fp16). PROJ=true: dense out.
// ===========================================================================
#define IK 128
#define IPITCH 144
#define IOFF_A2 (128*IPITCH)
#define IOFF_B1 (2*128*IPITCH)
#define IOFF_B2 (IOFF_B1 + 64*IPITCH)
#define ISTAGE (IOFF_B2 + 64*IPITCH)
#define IGEMM_DSMEM (2*ISTAGE)         // 110592

template<bool PROJ>
__global__ void __launch_bounds__(256, 2) gemm_i8(
    const int8_t* __restrict__ A1, const int8_t* __restrict__ A2,
    const int8_t* __restrict__ B1, const int8_t* __restrict__ B2,
    const float* __restrict__ sa_v, const float* __restrict__ sb_v,
    const float* __restrict__ bias, float* __restrict__ Cout)
{
    extern __shared__ char dsm_raw[];
    const uint32_t base = s2u(dsm_raw);

    const int tid  = threadIdx.x;
    const int wid  = tid >> 5, lane = tid & 31;
    const int bx = blockIdx.x, by = blockIdx.y;
    const int wm = wid >> 1, wn = wid & 1;    // warp tile 32(M) x 32(N)

    const int8_t* a1p = A1 + (size_t)(by * 128) * DM;
    const int8_t* a2p = A2 + (size_t)(by * 128) * DM;
    const int8_t* b1p = B1 + (size_t)(bx * 64) * DM;
    const int8_t* b2p = B2 + (size_t)(bx * 64) * DM;

    auto ISSUE = [&](int it) {
        const uint32_t sb = base + (it & 1) * ISTAGE;
        const int kof = it * IK;
        #pragma unroll
        for (int j = 0; j < 12; j++) {
            const int idx = tid + 256 * j;
            int local; uint32_t moff; const int8_t* srcp;
            if (j < 4)       { local = idx;        moff = 0;       srcp = a1p; }
            else if (j < 8)  { local = idx - 1024; moff = IOFF_A2; srcp = a2p; }
            else if (j < 10) { local = idx - 2048; moff = IOFF_B1; srcp = b1p; }
            else             { local = idx - 2560; moff = IOFF_B2; srcp = b2p; }
            const int r = local >> 3, c = local & 7;
            cpasync16(sb + moff + r * IPITCH + c * 16,
                      srcp + (size_t)r * DM + kof + c * 16);
        }
        CP_COMMIT();
    };

    int accP[2][4][4], accX[2][4][4];
    #pragma unroll
    for (int i = 0; i < 2; i++)
        #pragma unroll
        for (int j = 0; j < 4; j++)
            #pragma unroll
            for (int q = 0; q < 4; q++) { accP[i][j][q] = 0; accX[i][j][q] = 0; }

    ISSUE(0); ISSUE(1);

    const int NITI = DM / IK;
    for (int it = 0; it < NITI; ++it) {
        if (it == NITI - 1) { CP_WAIT0(); } else { CP_WAIT1(); }
        __syncthreads();

        const uint32_t sb = base + (it & 1) * ISTAGE;
        #pragma unroll
        for (int kc = 0; kc < 4; kc++) {
            uint32_t Ad1[2][4], Ad2[2][4];
            #pragma unroll
            for (int mf = 0; mf < 2; mf++) {
                const uint32_t aoff =
                    (uint32_t)((wm*32 + mf*16 + (lane & 15)) * IPITCH
                               + kc*32 + (lane >> 4) * 16);
                ldm_x4(Ad1[mf], sb + aoff);
                ldm_x4(Ad2[mf], sb + IOFF_A2 + aoff);
            }
            uint32_t Bd1[2][4], Bd2[2][4];
            #pragma unroll
            for (int g = 0; g < 2; g++) {
                const int quad = lane >> 3;
                const uint32_t boff =
                    (uint32_t)((wn*32 + g*16 + (quad >> 1) * 8 + (lane & 7)) * IPITCH
                               + kc*32 + (quad & 1) * 16);
                ldm_x4(Bd1[g], sb + IOFF_B1 + boff);
                ldm_x4(Bd2[g], sb + IOFF_B2 + boff);
            }
            #pragma unroll
            for (int mf = 0; mf < 2; mf++)
                #pragma unroll
                for (int nb = 0; nb < 4; nb++)
                    mma_s8(accP[mf][nb], Ad1[mf], Bd1[nb>>1][(nb&1)*2], Bd1[nb>>1][(nb&1)*2+1]);
            #pragma unroll
            for (int mf = 0; mf < 2; mf++)
                #pragma unroll
                for (int nb = 0; nb < 4; nb++)
                    mma_s8(accX[mf][nb], Ad1[mf], Bd2[nb>>1][(nb&1)*2], Bd2[nb>>1][(nb&1)*2+1]);
            #pragma unroll
            for (int mf = 0; mf < 2; mf++)
                #pragma unroll
                for (int nb = 0; nb < 4; nb++)
                    mma_s8(accX[mf][nb], Ad2[mf], Bd1[nb>>1][(nb&1)*2], Bd1[nb>>1][(nb&1)*2+1]);
        }
        __syncthreads();
        if (it + 2 < NITI) ISSUE(it + 2);
    }

    #pragma unroll
    for (int mf = 0; mf < 2; mf++)
        #pragma unroll
        for (int nb = 0; nb < 4; nb++)
            #pragma unroll
            for (int ci = 0; ci < 2; ci++) {
                const int m = by*128 + wm*32 + mf*16 + (lane >> 2) + ci*8;
                const int n = bx*64 + wn*32 + nb*8 + (lane & 3) * 2;
                const float sa = sa_v[m];
                float2 v;
                v.x = sa * sb_v[n]   * ((float)accP[mf][nb][2*ci+0]
                        + (float)accX[mf][nb][2*ci+0] * 0.004f) + bias[n];
                v.y = sa * sb_v[n+1] * ((float)accP[mf][nb][2*ci+1]
                        + (float)accX[mf][nb][2*ci+1] * 0.004f) + bias[n+1];
                if (PROJ) {
                    *(float2*)&Cout[(size_t)m * DM + n] = v;
                } else {
                    const int sel = n / DM;
                    const int r2  = n - sel * DM;
                    const int h   = r2 / HD;
                    const int dd  = r2 - h * HD;
                    const int bb  = m >> 10;
                    const int ss  = m & (SQ - 1);
                    const size_t di = (((size_t)bb * NH + h) * SQ + ss) * HD + dd;
                    if (sel == 0)      *(float2*)&g_q[di] = v;
                    else if (sel == 1) *(float2*)&g_k[di] = v;
                    else {
                        *(__half2*)&vh_g[di] = __floats2half2_rn(v.x, v.y);
                    }
                }
            }
}

// ---------------------------------------------------------------------------
// RoPE + int8 2-digit quantization, vectorized. One warp per (b,h,s) row.
// ---------------------------------------------------------------------------
__global__ void __launch_bounds__(256) rope_quant(
    const float* __restrict__ cosp, const float* __restrict__ sinp)
{
    const int row  = (blockIdx.x << 3) + (threadIdx.x >> 5);   // < NROWS
    const int lane = threadIdx.x & 31;
    const int ss   = row & (SQ - 1);
    const size_t base = (size_t)row * HD;
    const size_t rb   = (size_t)row * QPAD;

    const bool isQ = lane < 10;
    const bool isK = lane >= 10 && lane < 20;
    const int  i4  = isQ ? lane : (lane - 10);   // 0..9
    const int  d   = i4 * 4;

    float lo[4], hi[4];
    float m = 0.f;
    if (isQ || isK) {
        const float* t = isQ ? g_q : g_k;
        const float4 ta = *(const float4*)&t[base + d];
        const float4 tb = *(const float4*)&t[base + d + 40];
        const float4 ca = *(const float4*)&cosp[ss*HD + d];
        const float4 cb = *(const float4*)&cosp[ss*HD + d + 40];
        const float4 sa = *(const float4*)&sinp[ss*HD + d];
        const float4 sb = *(const float4*)&sinp[ss*HD + d + 40];
        lo[0] = ta.x*ca.x - tb.x*sa.x;  hi[0] = tb.x*cb.x + ta.x*sb.x;
        lo[1] = ta.y*ca.y - tb.y*sa.y;  hi[1] = tb.y*cb.y + ta.y*sb.y;
        lo[2] = ta.z*ca.z - tb.z*sa.z;  hi[2] = tb.z*cb.z + ta.z*sb.z;
        lo[3] = ta.w*ca.w - tb.w*sa.w;  hi[3] = tb.w*cb.w + ta.w*sb.w;
        #pragma unroll
        for (int e = 0; e < 4; e++)
            m = fmaxf(m, fmaxf(fabsf(lo[e]), fabsf(hi[e])));
    }

    float qm = isQ ? m : 0.f;
    float km = isK ? m : 0.f;
    #pragma unroll
    for (int off = 16; off >= 1; off >>= 1) {
        qm = fmaxf(qm, __shfl_xor_sync(0xffffffffu, qm, off));
        km = fmaxf(km, __shfl_xor_sync(0xffffffffu, km, off));
    }
    const float sq = (qm > 0.f) ? qm * (1.f/120.f) : 1.f;
    const float sk = (km > 0.f) ? km * (1.f/120.f) : 1.f;

    if (isQ || isK) {
        const float inv = isQ ? (1.f / sq) : (1.f / sk);
        int8_t* o1 = isQ ? qq1_g : kq1_g;
        int8_t* o2 = isQ ? qq2_g : kq2_g;
        uint32_t w1lo = 0, w2lo = 0, w1hi = 0, w2hi = 0;
        #pragma unroll
        for (int e = 0; e < 4; e++) {
            float f  = lo[e] * inv;
            float q1 = rintf(f);
            int   i1 = (int)q1;
            int   i2 = (int)rintf(250.f * (f - q1));
            w1lo |= (uint32_t)(i1 & 0xFF) << (8 * e);
            w2lo |= (uint32_t)(i2 & 0xFF) << (8 * e);
            f  = hi[e] * inv;
            q1 = rintf(f);
            i1 = (int)q1;
            i2 = (int)rintf(250.f * (f - q1));
            w1hi |= (uint32_t)(i1 & 0xFF) << (8 * e);
            w2hi |= (uint32_t)(i2 & 0xFF) << (8 * e);
        }
        *(uint32_t*)&o1[rb + d]      = w1lo;
        *(uint32_t*)&o2[rb + d]      = w2lo;
        *(uint32_t*)&o1[rb + d + 40] = w1hi;
        *(uint32_t*)&o2[rb + d + 40] = w2hi;
    } else if (lane < 24) {
        const size_t po = rb + 80 + (lane - 20) * 4;
        *(uint32_t*)&qq1_g[po] = 0u; *(uint32_t*)&qq2_g[po] = 0u;
        *(uint32_t*)&kq1_g[po] = 0u; *(uint32_t*)&kq2_g[po] = 0u;
    }
    if (lane == 0) { sq_g[row] = sq; sk_g[row] = sk; }
}

// ===========================================================================
// Flash attention: S-phase int8 2-digit, PV single-pass fp16.
// CTA = (q-tile 64 rows, bh), 4 warps (128 thr), 2 CTAs/SM.
// ===========================================================================
#define QIP 112                          // int8 row pitch in smem (96 + 16)
#define AQ1 0                            // Q digit 1: 64*112 = 7168
#define AQ2 7168
#define AKVQ 14336
#define SK1o 0
#define SK2o 7168
#define SVHo 14336
#define SSKo 25600                       // 64 floats (after 64*176 V bytes)
#define KVSTG 25856
#define ATTN_SMEM (AKVQ + 2*KVSTG)       // 66048
#define APITCH 176                       // fp16 V row pitch (160B data + pad)

__global__ void __launch_bounds__(128, 2) attn_tc()
{
    extern __shared__ char dsm_raw[];
    const uint32_t base = s2u(dsm_raw);

    const int tid = threadIdx.x;
    const int w = tid >> 5, lane = tid & 31;
    const int qt = blockIdx.x, bh = blockIdx.y;
    const int b = bh >> 4, h = bh & 15;
    const float scale = 0.11180339887498948f;  // 1/sqrt(80)

    const size_t row0 = (size_t)bh * SQ;
    const size_t qrow0 = row0 + qt * 64;

    auto ISSUE_KV = [&](int kt) {
        const uint32_t sb = base + AKVQ + (kt & 1) * KVSTG;
        const size_t kr = row0 + kt * 64;
        #pragma unroll
        for (int j = 0; j < 12; j++) {
            const int idx = tid + 128 * j;        // 0..1423 used
            if (idx < 384) {
                const int r = idx / 6, c = idx - r * 6;
                cpasync16(sb + SK1o + r * QIP + c * 16,
                          kq1_g + (kr + r) * QPAD + c * 16);
            } else if (idx < 768) {
                const int l = idx - 384, r = l / 6, c = l - r * 6;
                cpasync16(sb + SK2o + r * QIP + c * 16,
                          kq2_g + (kr + r) * QPAD + c * 16);
            } else if (idx < 1408) {
                const int l = idx - 768, r = l / 10, c = l - r * 10;
                cpasync16(sb + SVHo + r * APITCH + c * 16,
                          vh_g + (kr + r) * HD + c * 8);
            } else if (idx < 1424) {
                const int l = idx - 1408;
                cpasync16(sb + SSKo + l * 16, sk_g + kr + l * 4);
            }
        }
        CP_COMMIT();
    };

    // Q int8 tiles (once): 64 rows x 6 chunks x 2 mats = 768
    {
        #pragma unroll
        for (int j = 0; j < 6; j++) {
            const int idx = tid + 128 * j;
            const int mat = idx / 384;
            const int rem = idx - mat * 384;
            const int r = rem / 6, c = rem - r * 6;
            cpasync16(base + (mat ? AQ2 : AQ1) + r * QIP + c * 16,
                      (mat ? qq2_g : qq1_g) + (qrow0 + r) * QPAD + c * 16);
        }
        CP_COMMIT();
    }
    ISSUE_KV(0);

    const float sq0 = sq_g[qrow0 + w*16 + (lane >> 2)];
    const float sq1 = sq_g[qrow0 + w*16 + (lane >> 2) + 8];

    float oacc[10][4];
    #pragma unroll
    for (int i = 0; i < 10; i++)
        #pragma unroll
        for (int j = 0; j < 4; j++) oacc[i][j] = 0.f;
    float m0 = -1e30f, m1 = -1e30f, l0 = 0.f, l1 = 0.f;

    for (int kt = 0; kt < 16; kt++) {
        if (kt + 1 < 16) { ISSUE_KV(kt + 1); CP_WAIT1(); } else { CP_WAIT0(); }
        __syncthreads();

        const uint32_t kvb = base + AKVQ + (kt & 1) * KVSTG;
        const float* skf = (const float*)(dsm_raw + AKVQ + (kt & 1) * KVSTG + SSKo);

        // ---- S = Q K^T, int8 2-digit (3 k-chunks x 3 passes) ----
        int accP[8][4], accX[8][4];
        #pragma unroll
        for (int i = 0; i < 8; i++)
            #pragma unroll
            for (int j = 0; j < 4; j++) { accP[i][j] = 0; accX[i][j] = 0; }

        #pragma unroll
        for (int kc = 0; kc < 3; kc++) {
            uint32_t Ad1[4], Ad2[4];
            const uint32_t aoff =
                (uint32_t)((w*16 + (lane & 15)) * QIP + kc*32 + (lane >> 4) * 16);
            ldm_x4(Ad1, base + AQ1 + aoff);
            ldm_x4(Ad2, base + AQ2 + aoff);
            uint32_t Bd1[4][4], Bd2[4][4];
            #pragma unroll
            for (int g = 0; g < 4; g++) {
                const int quad = lane >> 3;
                const uint32_t boff =
                    (uint32_t)((g*16 + (quad >> 1) * 8 + (lane & 7)) * QIP
                               + kc*32 + (quad & 1) * 16);
                ldm_x4(Bd1[g], kvb + SK1o + boff);
                ldm_x4(Bd2[g], kvb + SK2o + boff);
            }
            #pragma unroll
            for (int nb = 0; nb < 8; nb++)
                mma_s8(accP[nb], Ad1, Bd1[nb>>1][(nb&1)*2], Bd1[nb>>1][(nb&1)*2+1]);
            #pragma unroll
            for (int nb = 0; nb < 8; nb++)
                mma_s8(accX[nb], Ad1, Bd2[nb>>1][(nb&1)*2], Bd2[nb>>1][(nb&1)*2+1]);
            #pragma unroll
            for (int nb = 0; nb < 8; nb++)
                mma_s8(accX[nb], Ad2, Bd1[nb>>1][(nb&1)*2], Bd1[nb>>1][(nb&1)*2+1]);
        }

        // ---- reconstruct scores + online softmax ----
        float sacc[8][4];
        #pragma unroll
        for (int nb = 0; nb < 8; nb++) {
            const int col = nb*8 + (lane & 3) * 2;
            const float k0 = skf[col] * scale, k1 = skf[col + 1] * scale;
            sacc[nb][0] = sq0 * k0 * ((float)accP[nb][0] + (float)accX[nb][0] * 0.004f);
            sacc[nb][1] = sq0 * k1 * ((float)accP[nb][1] + (float)accX[nb][1] * 0.004f);
            sacc[nb][2] = sq1 * k0 * ((float)accP[nb][2] + (float)accX[nb][2] * 0.004f);
            sacc[nb][3] = sq1 * k1 * ((float)accP[nb][3] + (float)accX[nb][3] * 0.004f);
        }

        float mx0 = -1e30f, mx1 = -1e30f;
        #pragma unroll
        for (int nb = 0; nb < 8; nb++) {
            mx0 = fmaxf(mx0, fmaxf(sacc[nb][0], sacc[nb][1]));
            mx1 = fmaxf(mx1, fmaxf(sacc[nb][2], sacc[nb][3]));
        }
        mx0 = fmaxf(mx0, __shfl_xor_sync(0xffffffffu, mx0, 1));
        mx0 = fmaxf(mx0, __shfl_xor_sync(0xffffffffu, mx0, 2));
        mx1 = fmaxf(mx1, __shfl_xor_sync(0xffffffffu, mx1, 1));
        mx1 = fmaxf(mx1, __shfl_xor_sync(0xffffffffu, mx1, 2));

        const float mn0 = fmaxf(m0, mx0), mn1 = fmaxf(m1, mx1);
        const float al0 = __expf(m0 - mn0), al1 = __expf(m1 - mn1);
        m0 = mn0; m1 = mn1;

        float rs0 = 0.f, rs1 = 0.f;
        #pragma unroll
        for (int nb = 0; nb < 8; nb++) {
            sacc[nb][0] = __expf(sacc[nb][0] - m0);
            sacc[nb][1] = __expf(sacc[nb][1] - m0);
            sacc[nb][2] = __expf(sacc[nb][2] - m1);
            sacc[nb][3] = __expf(sacc[nb][3] - m1);
            rs0 += sacc[nb][0] + sacc[nb][1];
            rs1 += sacc[nb][2] + sacc[nb][3];
        }
        rs0 += __shfl_xor_sync(0xffffffffu, rs0, 1);
        rs0 += __shfl_xor_sync(0xffffffffu, rs0, 2);
        rs1 += __shfl_xor_sync(0xffffffffu, rs1, 1);
        rs1 += __shfl_xor_sync(0xffffffffu, rs1, 2);
        l0 = l0 * al0 + rs0;
        l1 = l1 * al1 + rs1;

        #pragma unroll
        for (int nb = 0; nb < 10; nb++) {
            oacc[nb][0] *= al0; oacc[nb][1] *= al0;
            oacc[nb][2] *= al1; oacc[nb][3] *= al1;
        }

        // ---- O += P @ V, single-pass fp16 ----
        #pragma unroll
        for (int kc = 0; kc < 4; kc++) {
            uint32_t Pa[4];
            #pragma unroll
            for (int half2i = 0; half2i < 2; half2i++) {
                const int nb = 2*kc + half2i;
                Pa[2*half2i+0] = packh(sacc[nb][0], sacc[nb][1]);
                Pa[2*half2i+1] = packh(sacc[nb][2], sacc[nb][3]);
            }
            uint32_t Vh4[5][4];
            #pragma unroll
            for (int vg = 0; vg < 5; vg++) {
                const int vrow = kc*16 + ((lane >> 3) & 1) * 8 + (lane & 7);
                const int vcol = vg*16 + (lane >> 4) * 8;
                const uint32_t voff = (uint32_t)(vrow * APITCH + vcol * 2);
                ldm_x4_t(Vh4[vg], kvb + SVHo + voff);
            }
            #pragma unroll
            for (int vg = 0; vg < 5; vg++)
                #pragma unroll
                for (int hh = 0; hh < 2; hh++)
                    mma16816h(oacc[vg*2+hh], Pa, Vh4[vg][2*hh], Vh4[vg][2*hh+1]);
        }
        __syncthreads();
    }

    // ---- finalize: normalize, write fp32 ctx ----
    const float inv0 = 1.f / l0, inv1 = 1.f / l1;
    const int s0 = qt*64 + w*16 + (lane >> 2);
    const int s1 = s0 + 8;
    #pragma unroll
    for (int nb = 0; nb < 10; nb++) {
        const int d = nb*8 + (lane & 3) * 2;
        {
            float2 v; v.x = oacc[nb][0] * inv0; v.y = oacc[nb][1] * inv0;
            *(float2*)&g_ctx[((size_t)b * SQ + s0) * DM + h * HD + d] = v;
        }
        {
            float2 v; v.x = oacc[nb][2] * inv1; v.y = oacc[nb][3] * inv1;
            *(float2*)&g_ctx[((size_t)b * SQ + s1) * DM + h * HD + d] = v;
        }
    }
}

// ---------------------------------------------------------------------------
extern "C" void kernel_launch(void* const* d_in, const int* in_sizes, int n_in,
                              void* d_out, int out_size)
{
    (void)in_sizes; (void)n_in; (void)out_size;
    const float* x     = (const float*)d_in[0];
    const float* cosp  = (const float*)d_in[1];
    const float* sinp  = (const float*)d_in[2];
    const float* Wqkv  = (const float*)d_in[3];
    const float* bqkv  = (const float*)d_in[4];
    const float* Wproj = (const float*)d_in[5];
    const float* bproj = (const float*)d_in[6];
    float* out = (float*)d_out;

    cudaFuncSetAttribute(gemm_i8<false>,
                         cudaFuncAttributeMaxDynamicSharedMemorySize, IGEMM_DSMEM);
    cudaFuncSetAttribute(gemm_i8<true>,
                         cudaFuncAttributeMaxDynamicSharedMemorySize, IGEMM_DSMEM);
    cudaFuncSetAttribute(attn_tc,
                         cudaFuncAttributeMaxDynamicSharedMemorySize, ATTN_SMEM);

    int8_t *xq1, *xq2, *wq1, *wq2;
    float *sax, *sbw, *ctx;
    cudaGetSymbolAddress((void**)&xq1, xq1_g);
    cudaGetSymbolAddress((void**)&xq2, xq2_g);
    cudaGetSymbolAddress((void**)&wq1, wq1_g);
    cudaGetSymbolAddress((void**)&wq2, wq2_g);
    cudaGetSymbolAddress((void**)&sax, sax_g);
    cudaGetSymbolAddress((void**)&sbw, sbw_g);
    cudaGetSymbolAddress((void**)&ctx, g_ctx);

    // 0) fused quantize: x + Wqkv
    quant2_kernel<<<MTOT + NQKV, 128>>>(x, xq1, xq2, sax, MTOT,
                                        Wqkv, wq1, wq2, sbw);
    // 1) QKV GEMM (int8): q,k fp32 head-major + v fp16
    gemm_i8<false><<<dim3(NQKV/64, MTOT/128), 256, IGEMM_DSMEM>>>(
        xq1, xq2, wq1, wq2, sax, sbw, bqkv, nullptr);
    // 2) RoPE + int8 quant -> qq/kq + scales (vectorized)
    rope_quant<<<NROWS/8, 256>>>(cosp, sinp);
    // 3) attention (int8 S, fp16 single-pass PV; 64-row tiles, 2 CTAs/SM)
    attn_tc<<<dim3(SQ/64, NB*NH), 128, ATTN_SMEM>>>();
    // 4) fused quantize: ctx + Wproj (reusing digit buffers)
    quant2_kernel<<<MTOT + DM, 128>>>(ctx, xq1, xq2, sax, MTOT,
                                      Wproj, wq1, wq2, sbw);
    // 5) output projection (int8) -> d_out
    gemm_i8<true><<<dim3(DM/64, MTOT/128), 256, IGEMM_DSMEM>>>(
        xq1, xq2, wq1, wq2, sax, sbw, bproj, out);
}